// round 2
// baseline (speedup 1.0000x reference)
#include <cuda_runtime.h>
#include <math.h>

#define B_  8
#define CIN 64
#define H_  128
#define W_  128
#define HO  64
#define WO  128
#define CO  64

typedef unsigned long long ull;

// Scratch (no allocations allowed -> __device__ globals)
__device__ float g_offmask[B_*27*HO*WO];   // ch 0..17 offsets, 18..26 sigmoid(mask)
__device__ float g_Wom[576*28];            // [c*9+k][o] padded to 28 o's
__device__ float g_bias[28];
__device__ float g_Wt[9*64*64];            // [k][c][o]

// ---- packed f32x2 helpers ----
__device__ __forceinline__ void ffma2(ull& d, ull a, ull b) {
    asm("fma.rn.f32x2 %0, %1, %2, %3;" : "=l"(d) : "l"(a), "l"(b), "l"(d));
}
__device__ __forceinline__ ull pack2(float lo, float hi) {
    ull r; asm("mov.b64 %0, {%1, %2};" : "=l"(r) : "f"(lo), "f"(hi));
    return r;
}
__device__ __forceinline__ float2 unpack2(ull v) {
    float2 r; asm("mov.b64 {%0, %1}, %2;" : "=f"(r.x), "=f"(r.y) : "l"(v));
    return r;
}

// ---------------------------------------------------------------------------
// Kernel 0: weight transpose / repack
// ---------------------------------------------------------------------------
__global__ void prep_kernel(const float* __restrict__ w_off, const float* __restrict__ b_off,
                            const float* __restrict__ w_mask, const float* __restrict__ b_mask,
                            const float* __restrict__ w_conv) {
    int idx = blockIdx.x * blockDim.x + threadIdx.x;
    if (idx < 9*64*64) {
        int k = idx >> 12; int r = idx & 4095; int c = r >> 6; int o = r & 63;
        g_Wt[idx] = w_conv[(o*64 + c)*9 + k];
    }
    if (idx < 576*28) {
        int ck = idx / 28; int o = idx % 28;
        int c = ck / 9; int k = ck % 9;
        float v = 0.f;
        if (o < 18)       v = w_off[(o*64 + c)*9 + k];
        else if (o < 27)  v = w_mask[((o-18)*64 + c)*9 + k];
        g_Wom[idx] = v;
    }
    if (idx < 28) {
        float v = 0.f;
        if (idx < 18)      v = b_off[idx];
        else if (idx < 27) v = b_mask[idx - 18];
        g_bias[idx] = v;
    }
}

// ---------------------------------------------------------------------------
// Kernel 1: offset + mask conv (27 out-ch, stride (2,1), pad (1,1)) via FFMA2
// Block: 224 threads = 32 px * 7 groups of 4 out-ch.
// Smem: duplicated x patch float2[64*102] (52,224B) + weights[576*28] (64,512B)
//       = 116,736B -> 2 blocks/SM.
// ---------------------------------------------------------------------------
__global__ void __launch_bounds__(224) conv_om_kernel(const float* __restrict__ x) {
    extern __shared__ float smem_raw[];
    float2* spd = (float2*)smem_raw;                 // 64*102 float2
    float*  sw  = smem_raw + 64*102*2;               // 576*28 floats

    int tid = threadIdx.x;
    int wo0 = blockIdx.x * 32;
    int ho  = blockIdx.y;
    int b   = blockIdx.z;

    // weights -> smem (coalesced float4)
    {
        float4* d4 = (float4*)sw;
        const float4* s4 = (const float4*)g_Wom;
        for (int t = tid; t < (576*28)/4; t += 224) d4[t] = s4[t];
    }
    // x patch -> smem, value duplicated into both float2 lanes
    const float* xb = x + (size_t)b * CIN * H_ * W_;
    for (int t = tid; t < 64*102; t += 224) {
        int c = t / 102; int r = t % 102; int ky = r / 34; int col = r % 34;
        int gy = 2*ho - 1 + ky;
        int gx = wo0 - 1 + col;
        float v = 0.f;
        if (gy >= 0 && gy < H_ && gx >= 0 && gx < W_)
            v = xb[(c*H_ + gy)*W_ + gx];
        spd[t] = make_float2(v, v);
    }
    __syncthreads();

    int px = tid & 31;
    int o0 = (tid >> 5) * 4;           // 0,4,...,24
    ull acc01 = pack2(g_bias[o0+0], g_bias[o0+1]);
    ull acc23 = pack2(g_bias[o0+2], g_bias[o0+3]);

    for (int c = 0; c < 64; ++c) {
        const float2* prow = spd + c*102;
        #pragma unroll
        for (int ky = 0; ky < 3; ++ky) {
            #pragma unroll
            for (int kx = 0; kx < 3; ++kx) {
                ull pv = *(const ull*)&prow[ky*34 + px + kx];
                ulonglong2 w2 = *(const ulonglong2*)&sw[(c*9 + ky*3 + kx)*28 + o0];
                ffma2(acc01, w2.x, pv);
                ffma2(acc23, w2.y, pv);
            }
        }
    }

    int wo = wo0 + px;
    float2 r01 = unpack2(acc01), r23 = unpack2(acc23);
    float accs[4] = {r01.x, r01.y, r23.x, r23.y};
    #pragma unroll
    for (int j = 0; j < 4; ++j) {
        int o = o0 + j;
        if (o < 27) {
            float v = accs[j];
            if (o >= 18) v = 1.f / (1.f + expf(-v));   // sigmoid for mask channels
            g_offmask[((b*27 + o)*HO + ho)*WO + wo] = v;
        }
    }
}

// ---------------------------------------------------------------------------
// Kernel 2: fused bilinear gather + 64x576 GEMM via FFMA2
// Block: 256 threads = 32 px * 8 groups of 8 out-ch.
// ---------------------------------------------------------------------------
__global__ void __launch_bounds__(256) deform_kernel(const float* __restrict__ x,
                                                     float* __restrict__ out) {
    __shared__ float2 sSd[64][33];   // sampled value duplicated (v,v), padded rows
    __shared__ float  sW[64*64];     // W_k, [c][o]
    __shared__ float  s_cw[4][288];  // 4 corner weights (validity & mask folded in)
    __shared__ int    s_iy0[288], s_iy1[288], s_ix0[288], s_ix1[288];

    int tid = threadIdx.x;
    int wo0 = blockIdx.x * 32;
    int ho  = blockIdx.y;
    int b   = blockIdx.z;

    // Precompute all 9x32 bilinear metadata once
    for (int t = tid; t < 288; t += 256) {
        int k = t >> 5; int p = t & 31; int wo = wo0 + p;
        const float* om = g_offmask + (size_t)b*27*HO*WO;
        float offy = om[((2*k)   * HO + ho)*WO + wo];
        float offx = om[((2*k+1) * HO + ho)*WO + wo];
        float m    = om[((18+k)  * HO + ho)*WO + wo];
        float py  = offy + (float)(k/3) + (float)(2*ho - 1);
        float pxx = offx + (float)(k%3) + (float)(wo - 1);
        float y0f = floorf(py),  x0f = floorf(pxx);
        float dy = py - y0f,     dx = pxx - x0f;
        int y0 = (int)y0f, x0i = (int)x0f;
        int y1 = y0 + 1,   x1  = x0i + 1;
        bool vy0 = (y0  >= 0) && (y0  < H_);
        bool vy1 = (y1  >= 0) && (y1  < H_);
        bool vx0 = (x0i >= 0) && (x0i < W_);
        bool vx1 = (x1  >= 0) && (x1  < W_);
        s_cw[0][t] = (1.f-dy)*(1.f-dx)*m * ((vy0 && vx0) ? 1.f : 0.f);
        s_cw[1][t] = (1.f-dy)*dx      *m * ((vy0 && vx1) ? 1.f : 0.f);
        s_cw[2][t] = dy*(1.f-dx)      *m * ((vy1 && vx0) ? 1.f : 0.f);
        s_cw[3][t] = dy*dx            *m * ((vy1 && vx1) ? 1.f : 0.f);
        s_iy0[t] = min(max(y0, 0),  H_-1);
        s_iy1[t] = min(max(y1, 0),  H_-1);
        s_ix0[t] = min(max(x0i, 0), W_-1);
        s_ix1[t] = min(max(x1, 0),  W_-1);
    }

    ull acc[4];   // 8 outputs as 4 packed pairs
    #pragma unroll
    for (int j = 0; j < 4; ++j) acc[j] = 0ull;

    int p   = tid & 31;
    int grp = tid >> 5;
    int o0  = grp * 8;
    const float* xb = x + (size_t)b * CIN * H_ * W_;

    #pragma unroll 1
    for (int k = 0; k < 9; ++k) {
        __syncthreads();   // orders metadata (k==0) and guards smem reuse
        // stage W_k (coalesced)
        {
            float4* d4 = (float4*)sW;
            const float4* s4 = (const float4*)(g_Wt + k*4096);
            for (int t = tid; t < 1024; t += 256) d4[t] = s4[t];
        }
        // gather: 8 channels per thread, 4 corner loads each
        {
            int mb = (k << 5) + p;
            int iy0 = s_iy0[mb]*W_, iy1 = s_iy1[mb]*W_;
            int ix0 = s_ix0[mb],    ix1 = s_ix1[mb];
            float w00 = s_cw[0][mb], w01 = s_cw[1][mb];
            float w10 = s_cw[2][mb], w11 = s_cw[3][mb];
            #pragma unroll
            for (int i = 0; i < 8; ++i) {
                int c = grp*8 + i;
                const float* xc = xb + c*(H_*W_);
                float v = w00*__ldg(xc + iy0 + ix0)
                        + w01*__ldg(xc + iy0 + ix1)
                        + w10*__ldg(xc + iy1 + ix0)
                        + w11*__ldg(xc + iy1 + ix1);
                sSd[c][p] = make_float2(v, v);
            }
        }
        __syncthreads();
        // GEMM accumulate: acc[o0..o0+7] += W_k[c][o] * S[c][px]
        #pragma unroll 8
        for (int c = 0; c < 64; ++c) {
            ull sv = *(const ull*)&sSd[c][p];
            ulonglong2 wa = *(const ulonglong2*)&sW[c*64 + o0];      // o0..o0+3
            ulonglong2 wb = *(const ulonglong2*)&sW[c*64 + o0 + 4];  // o0+4..o0+7
            ffma2(acc[0], wa.x, sv);
            ffma2(acc[1], wa.y, sv);
            ffma2(acc[2], wb.x, sv);
            ffma2(acc[3], wb.y, sv);
        }
    }

    #pragma unroll
    for (int j = 0; j < 4; ++j) {
        float2 r = unpack2(acc[j]);
        out[(((size_t)b*CO + o0 + 2*j    )*HO + ho)*WO + wo0 + p] = r.x;
        out[(((size_t)b*CO + o0 + 2*j + 1)*HO + ho)*WO + wo0 + p] = r.y;
    }
}

// ---------------------------------------------------------------------------
extern "C" void kernel_launch(void* const* d_in, const int* in_sizes, int n_in,
                              void* d_out, int out_size) {
    const float* x      = (const float*)d_in[0];
    const float* b_off  = (const float*)d_in[2];
    const float* w_off  = (const float*)d_in[1];
    const float* w_mask = (const float*)d_in[3];
    const float* b_mask = (const float*)d_in[4];
    const float* w_conv = (const float*)d_in[5];
    float* out = (float*)d_out;

    prep_kernel<<<144, 256>>>(w_off, b_off, w_mask, b_mask, w_conv);

    int smem1 = (64*102*2 + 576*28) * (int)sizeof(float);   // 116,736 B
    cudaFuncSetAttribute((const void*)conv_om_kernel,
                         cudaFuncAttributeMaxDynamicSharedMemorySize, smem1);
    conv_om_kernel<<<dim3(4, 64, 8), 224, smem1>>>(x);

    deform_kernel<<<dim3(4, 64, 8), 256>>>(x, out);
}

// round 3
// speedup vs baseline: 1.3418x; 1.3418x over previous
#include <cuda_runtime.h>
#include <math.h>

#define B_  8
#define CIN 64
#define H_  128
#define W_  128
#define HO  64
#define WO  128
#define CO  64

// Scratch (no allocations allowed -> __device__ globals)
__device__ float g_offmask[B_*27*HO*WO];   // ch 0..17 offsets, 18..26 sigmoid(mask)
__device__ float g_Wom[576*32];            // [c*9+k][o] padded to 32 o's
__device__ float g_bias[32];
__device__ float g_Wt[9*64*64];            // [k][c][o]

__device__ __forceinline__ unsigned smem_u32(const void* p) {
    unsigned a;
    asm("{ .reg .u64 t; cvta.to.shared.u64 t, %1; cvt.u32.u64 %0, t; }" : "=r"(a) : "l"(p));
    return a;
}

// ---------------------------------------------------------------------------
// Kernel 0: weight transpose / repack (coalesced consumers later)
// ---------------------------------------------------------------------------
__global__ void prep_kernel(const float* __restrict__ w_off, const float* __restrict__ b_off,
                            const float* __restrict__ w_mask, const float* __restrict__ b_mask,
                            const float* __restrict__ w_conv) {
    int idx = blockIdx.x * blockDim.x + threadIdx.x;
    if (idx < 9*64*64) {
        int k = idx >> 12; int r = idx & 4095; int c = r >> 6; int o = r & 63;
        g_Wt[idx] = w_conv[(o*64 + c)*9 + k];
    }
    if (idx < 576*32) {
        int ck = idx >> 5; int o = idx & 31;
        int c = ck / 9; int k = ck % 9;
        float v = 0.f;
        if (o < 18)       v = w_off[(o*64 + c)*9 + k];
        else if (o < 27)  v = w_mask[((o-18)*64 + c)*9 + k];
        g_Wom[idx] = v;
    }
    if (idx < 32) {
        float v = 0.f;
        if (idx < 18)      v = b_off[idx];
        else if (idx < 27) v = b_mask[idx - 18];
        g_bias[idx] = v;
    }
}

// ---------------------------------------------------------------------------
// Kernel 1: offset + mask conv (27 out-ch, stride (2,1), pad (1,1))
// (identical to R1 — known good)
// ---------------------------------------------------------------------------
__global__ void __launch_bounds__(256) conv_om_kernel(const float* __restrict__ x) {
    extern __shared__ float smem[];
    float* sp = smem;              // 64*102 = 6528 floats
    float* sw = smem + 6528;       // 576*32 = 18432 floats

    int tid = threadIdx.x;
    int wo0 = blockIdx.x * 32;
    int ho  = blockIdx.y;
    int b   = blockIdx.z;

    {
        float4* d4 = (float4*)sw;
        const float4* s4 = (const float4*)g_Wom;
        for (int t = tid; t < 18432/4; t += 256) d4[t] = s4[t];
    }
    const float* xb = x + (size_t)b * CIN * H_ * W_;
    for (int t = tid; t < 64*102; t += 256) {
        int c = t / 102; int r = t % 102; int ky = r / 34; int col = r % 34;
        int gy = 2*ho - 1 + ky;
        int gx = wo0 - 1 + col;
        float v = 0.f;
        if (gy >= 0 && gy < H_ && gx >= 0 && gx < W_)
            v = xb[(c*H_ + gy)*W_ + gx];
        sp[t] = v;
    }
    __syncthreads();

    int px = tid & 31;
    int o0 = (tid >> 5) * 4;
    float acc0 = g_bias[o0+0], acc1 = g_bias[o0+1];
    float acc2 = g_bias[o0+2], acc3 = g_bias[o0+3];

    for (int c = 0; c < 64; ++c) {
        const float* prow = sp + c*102;
        #pragma unroll
        for (int ky = 0; ky < 3; ++ky) {
            #pragma unroll
            for (int kx = 0; kx < 3; ++kx) {
                float pv = prow[ky*34 + px + kx];
                int ck = c*9 + ky*3 + kx;
                float4 w = *(const float4*)&sw[ck*32 + o0];
                acc0 += w.x*pv; acc1 += w.y*pv; acc2 += w.z*pv; acc3 += w.w*pv;
            }
        }
    }

    int wo = wo0 + px;
    float accs[4] = {acc0, acc1, acc2, acc3};
    #pragma unroll
    for (int j = 0; j < 4; ++j) {
        int o = o0 + j;
        if (o < 27) {
            float v = accs[j];
            if (o >= 18) v = 1.f / (1.f + expf(-v));
            g_offmask[((b*27 + o)*HO + ho)*WO + wo] = v;
        }
    }
}

// ---------------------------------------------------------------------------
// Kernel 2: fused bilinear gather + 64x576 GEMM, software-pipelined.
// Double-buffered sS and sW; corner LDGs for k+1 and cp.async of W[k+1] are
// issued before the GEMM on k so their latency is hidden under 512 FFMAs.
// Block: 256 threads = 32 px * 8 groups of 8 out-ch.
// Smem (dynamic): sW[2][4096] + sS[2][64*33] + meta  ~= 58.9 KB -> 3 blocks/SM.
// ---------------------------------------------------------------------------
__global__ void __launch_bounds__(256) deform_kernel(const float* __restrict__ x,
                                                     float* __restrict__ out) {
    extern __shared__ float sm[];
    float* sW   = sm;                    // 2*4096
    float* sS   = sm + 8192;             // 2*(64*33) = 2*2112
    float* s_cw = sm + 8192 + 4224;      // 4*288
    int*   s_iy0 = (int*)(s_cw + 4*288); // 288 each
    int*   s_iy1 = s_iy0 + 288;
    int*   s_ix0 = s_iy1 + 288;
    int*   s_ix1 = s_ix0 + 288;

    int tid = threadIdx.x;
    int wo0 = blockIdx.x * 32;
    int ho  = blockIdx.y;
    int b   = blockIdx.z;
    int p   = tid & 31;
    int grp = tid >> 5;
    int o0  = grp * 8;

    // Bilinear metadata for all 9x32 samples
    for (int t = tid; t < 288; t += 256) {
        int k = t >> 5; int pp = t & 31; int wo = wo0 + pp;
        const float* om = g_offmask + (size_t)b*27*HO*WO;
        float offy = om[((2*k)   * HO + ho)*WO + wo];
        float offx = om[((2*k+1) * HO + ho)*WO + wo];
        float m    = om[((18+k)  * HO + ho)*WO + wo];
        float py  = offy + (float)(k/3) + (float)(2*ho - 1);
        float pxx = offx + (float)(k%3) + (float)(wo - 1);
        float y0f = floorf(py),  x0f = floorf(pxx);
        float dy = py - y0f,     dx = pxx - x0f;
        int y0 = (int)y0f, x0i = (int)x0f;
        int y1 = y0 + 1,   x1  = x0i + 1;
        bool vy0 = (y0  >= 0) && (y0  < H_);
        bool vy1 = (y1  >= 0) && (y1  < H_);
        bool vx0 = (x0i >= 0) && (x0i < W_);
        bool vx1 = (x1  >= 0) && (x1  < W_);
        s_cw[0*288 + t] = (1.f-dy)*(1.f-dx)*m * ((vy0 && vx0) ? 1.f : 0.f);
        s_cw[1*288 + t] = (1.f-dy)*dx      *m * ((vy0 && vx1) ? 1.f : 0.f);
        s_cw[2*288 + t] = dy*(1.f-dx)      *m * ((vy1 && vx0) ? 1.f : 0.f);
        s_cw[3*288 + t] = dy*dx            *m * ((vy1 && vx1) ? 1.f : 0.f);
        s_iy0[t] = min(max(y0, 0),  H_-1);
        s_iy1[t] = min(max(y1, 0),  H_-1);
        s_ix0[t] = min(max(x0i, 0), W_-1);
        s_ix1[t] = min(max(x1, 0),  W_-1);
    }
    __syncthreads();

    const float* xb = x + (size_t)b * CIN * H_ * W_;

    float rv[32];   // 8 channels x 4 corners, raw loads for the *next* k
    float acc[8];
    #pragma unroll
    for (int j = 0; j < 8; ++j) acc[j] = 0.f;

    // ---- prologue: stage W[0] via cp.async, issue corner LDGs for k=0 ----
    {
        unsigned sdst = smem_u32(sW) + tid * 16;
        const float* gsrc = g_Wt + (size_t)tid * 4;
        #pragma unroll
        for (int j = 0; j < 4; ++j)
            asm volatile("cp.async.cg.shared.global [%0], [%1], 16;"
                         :: "r"(sdst + j*4096u), "l"(gsrc + j*1024) : "memory");
        asm volatile("cp.async.commit_group;" ::: "memory");
    }
    {
        int mb = p;   // k = 0
        int iy0 = s_iy0[mb]*W_, iy1 = s_iy1[mb]*W_;
        int ix0 = s_ix0[mb],    ix1 = s_ix1[mb];
        #pragma unroll
        for (int i = 0; i < 8; ++i) {
            const float* xc = xb + (grp*8 + i)*(H_*W_);
            rv[4*i+0] = __ldg(xc + iy0 + ix0);
            rv[4*i+1] = __ldg(xc + iy0 + ix1);
            rv[4*i+2] = __ldg(xc + iy1 + ix0);
            rv[4*i+3] = __ldg(xc + iy1 + ix1);
        }
    }
    asm volatile("cp.async.wait_group 0;" ::: "memory");

    #pragma unroll 1
    for (int k = 0; k < 9; ++k) {
        int cur = k & 1, nxt = cur ^ 1;

        // combine corner loads (issued last iter) -> sS[cur]
        {
            int mb = (k << 5) + p;
            float w00 = s_cw[0*288 + mb], w01 = s_cw[1*288 + mb];
            float w10 = s_cw[2*288 + mb], w11 = s_cw[3*288 + mb];
            float* Sc = sS + cur*2112;
            #pragma unroll
            for (int i = 0; i < 8; ++i) {
                float v = w00*rv[4*i+0] + w01*rv[4*i+1]
                        + w10*rv[4*i+2] + w11*rv[4*i+3];
                Sc[(grp*8 + i)*33 + p] = v;
            }
        }
        __syncthreads();   // sS[cur] visible; sW[cur] (cp.async'd last iter) visible

        if (k < 8) {
            // stage W[k+1] into sW[nxt] (cp.async, waits after GEMM)
            unsigned sdst = smem_u32(sW) + nxt*16384u + tid*16;
            const float* gsrc = g_Wt + (size_t)(k+1)*4096 + tid*4;
            #pragma unroll
            for (int j = 0; j < 4; ++j)
                asm volatile("cp.async.cg.shared.global [%0], [%1], 16;"
                             :: "r"(sdst + j*4096u), "l"(gsrc + j*1024) : "memory");
            asm volatile("cp.async.commit_group;" ::: "memory");
            // issue corner LDGs for k+1 (consumed next iteration)
            int mb = ((k+1) << 5) + p;
            int iy0 = s_iy0[mb]*W_, iy1 = s_iy1[mb]*W_;
            int ix0 = s_ix0[mb],    ix1 = s_ix1[mb];
            #pragma unroll
            for (int i = 0; i < 8; ++i) {
                const float* xc = xb + (grp*8 + i)*(H_*W_);
                rv[4*i+0] = __ldg(xc + iy0 + ix0);
                rv[4*i+1] = __ldg(xc + iy0 + ix1);
                rv[4*i+2] = __ldg(xc + iy1 + ix0);
                rv[4*i+3] = __ldg(xc + iy1 + ix1);
            }
        }

        // GEMM on current buffers: acc[o0..o0+7] += W_k[c][o] * S[c][px]
        {
            const float* Wc = sW + cur*4096;
            const float* Sc = sS + cur*2112;
            #pragma unroll 8
            for (int c = 0; c < 64; ++c) {
                float sv = Sc[c*33 + p];
                float4 wa = *(const float4*)&Wc[c*64 + o0];
                float4 wb = *(const float4*)&Wc[c*64 + o0 + 4];
                acc[0] += wa.x*sv; acc[1] += wa.y*sv;
                acc[2] += wa.z*sv; acc[3] += wa.w*sv;
                acc[4] += wb.x*sv; acc[5] += wb.y*sv;
                acc[6] += wb.z*sv; acc[7] += wb.w*sv;
            }
        }
        if (k < 8)
            asm volatile("cp.async.wait_group 0;" ::: "memory");
    }

    #pragma unroll
    for (int j = 0; j < 8; ++j)
        out[(((size_t)b*CO + o0 + j)*HO + ho)*WO + wo0 + p] = acc[j];
}

// ---------------------------------------------------------------------------
extern "C" void kernel_launch(void* const* d_in, const int* in_sizes, int n_in,
                              void* d_out, int out_size) {
    const float* x      = (const float*)d_in[0];
    const float* w_off  = (const float*)d_in[1];
    const float* b_off  = (const float*)d_in[2];
    const float* w_mask = (const float*)d_in[3];
    const float* b_mask = (const float*)d_in[4];
    const float* w_conv = (const float*)d_in[5];
    float* out = (float*)d_out;

    prep_kernel<<<144, 256>>>(w_off, b_off, w_mask, b_mask, w_conv);

    int smem1 = (6528 + 18432) * (int)sizeof(float);   // 99,840 B
    cudaFuncSetAttribute((const void*)conv_om_kernel,
                         cudaFuncAttributeMaxDynamicSharedMemorySize, smem1);
    conv_om_kernel<<<dim3(4, 64, 8), 256, smem1>>>(x);

    int smem2 = (8192 + 4224 + 4*288) * (int)sizeof(float) + 4*288*(int)sizeof(int); // 58,880 B
    cudaFuncSetAttribute((const void*)deform_kernel,
                         cudaFuncAttributeMaxDynamicSharedMemorySize, smem2);
    deform_kernel<<<dim3(4, 64, 8), 256, smem2>>>(x, out);
}

// round 5
// speedup vs baseline: 1.8170x; 1.3541x over previous
#include <cuda_runtime.h>
#include <cuda_bf16.h>
#include <math.h>
#include <stdint.h>

#define B_  8
#define CIN 64
#define H_  128
#define W_  128
#define HO  64
#define WO  128
#define CO  64
#define HW_ (H_*W_)

// Scratch (no allocations allowed -> __device__ globals)
__device__ float g_offmask[B_*27*HO*WO];   // ch 0..17 offsets, 18..26 sigmoid(mask)
__device__ float g_Wom[576*32];            // [c*9+k][o] padded to 32 o's
__device__ float g_bias[32];
// Per tap k: 8KB hi + 8KB lo; rows = out-channel o (64), cols = c (64 bf16 = 128B),
// SW128-swizzled so kernels can bulk-copy 16B chunks verbatim and ldmatrix directly.
__device__ __align__(16) char g_Wsplit[9*16384];

__device__ __forceinline__ uint32_t smem_u32(const void* p) {
    uint32_t a;
    asm("{ .reg .u64 t; cvta.to.shared.u64 t, %1; cvt.u32.u64 %0, t; }" : "=r"(a) : "l"(p));
    return a;
}
__device__ __forceinline__ uint32_t sw128(uint32_t off) { return off ^ ((off >> 3) & 0x70); }

#define LDMATRIX_X4(r0,r1,r2,r3,addr) \
    asm volatile("ldmatrix.sync.aligned.m8n8.x4.shared.b16 {%0,%1,%2,%3}, [%4];" \
                 : "=r"(r0),"=r"(r1),"=r"(r2),"=r"(r3) : "r"(addr))

#define MMA_BF16(c, a0,a1,a2,a3, b0,b1) \
    asm volatile("mma.sync.aligned.m16n8k16.row.col.f32.bf16.bf16.f32 " \
                 "{%0,%1,%2,%3},{%4,%5,%6,%7},{%8,%9},{%0,%1,%2,%3};" \
                 : "+f"((c)[0]),"+f"((c)[1]),"+f"((c)[2]),"+f"((c)[3]) \
                 : "r"(a0),"r"(a1),"r"(a2),"r"(a3), "r"(b0),"r"(b1))

// ---------------------------------------------------------------------------
// Kernel 0: weight repack (conv_om weights + hi/lo-split swizzled GEMM weights)
// ---------------------------------------------------------------------------
__global__ void prep_kernel(const float* __restrict__ w_off, const float* __restrict__ b_off,
                            const float* __restrict__ w_mask, const float* __restrict__ b_mask,
                            const float* __restrict__ w_conv) {
    int idx = blockIdx.x * blockDim.x + threadIdx.x;
    if (idx < 9*64*64) {
        int k = idx / 4096; int r = idx & 4095; int o = r >> 6; int c = r & 63;
        float w = w_conv[(o*64 + c)*9 + k];
        __nv_bfloat16 hi = __float2bfloat16(w);
        float hif = __bfloat162float(hi);
        __nv_bfloat16 lo = __float2bfloat16(w - hif);
        uint32_t sw = sw128((uint32_t)(o*128 + c*2));
        *(__nv_bfloat16*)(g_Wsplit + k*16384 + sw)        = hi;
        *(__nv_bfloat16*)(g_Wsplit + k*16384 + 8192 + sw) = lo;
    }
    if (idx < 576*32) {
        int ck = idx >> 5; int o = idx & 31;
        int c = ck / 9; int k = ck % 9;
        float v = 0.f;
        if (o < 18)       v = w_off[(o*64 + c)*9 + k];
        else if (o < 27)  v = w_mask[((o-18)*64 + c)*9 + k];
        g_Wom[idx] = v;
    }
    if (idx < 32) {
        float v = 0.f;
        if (idx < 18)      v = b_off[idx];
        else if (idx < 27) v = b_mask[idx - 18];
        g_bias[idx] = v;
    }
}

// ---------------------------------------------------------------------------
// Kernel 1: offset + mask conv (unchanged from best-known R1)
// ---------------------------------------------------------------------------
__global__ void __launch_bounds__(256) conv_om_kernel(const float* __restrict__ x) {
    extern __shared__ float smem[];
    float* sp = smem;              // 64*102
    float* sw = smem + 6528;       // 576*32

    int tid = threadIdx.x;
    int wo0 = blockIdx.x * 32;
    int ho  = blockIdx.y;
    int b   = blockIdx.z;

    {
        float4* d4 = (float4*)sw;
        const float4* s4 = (const float4*)g_Wom;
        for (int t = tid; t < 18432/4; t += 256) d4[t] = s4[t];
    }
    const float* xb = x + (size_t)b * CIN * H_ * W_;
    for (int t = tid; t < 64*102; t += 256) {
        int c = t / 102; int r = t % 102; int ky = r / 34; int col = r % 34;
        int gy = 2*ho - 1 + ky;
        int gx = wo0 - 1 + col;
        float v = 0.f;
        if (gy >= 0 && gy < H_ && gx >= 0 && gx < W_)
            v = xb[(c*H_ + gy)*W_ + gx];
        sp[t] = v;
    }
    __syncthreads();

    int px = tid & 31;
    int o0 = (tid >> 5) * 4;
    float acc0 = g_bias[o0+0], acc1 = g_bias[o0+1];
    float acc2 = g_bias[o0+2], acc3 = g_bias[o0+3];

    for (int c = 0; c < 64; ++c) {
        const float* prow = sp + c*102;
        #pragma unroll
        for (int ky = 0; ky < 3; ++ky) {
            #pragma unroll
            for (int kx = 0; kx < 3; ++kx) {
                float pv = prow[ky*34 + px + kx];
                int ck = c*9 + ky*3 + kx;
                float4 w = *(const float4*)&sw[ck*32 + o0];
                acc0 += w.x*pv; acc1 += w.y*pv; acc2 += w.z*pv; acc3 += w.w*pv;
            }
        }
    }

    int wo = wo0 + px;
    float accs[4] = {acc0, acc1, acc2, acc3};
    #pragma unroll
    for (int j = 0; j < 4; ++j) {
        int o = o0 + j;
        if (o < 27) {
            float v = accs[j];
            if (o >= 18) v = 1.f / (1.f + expf(-v));
            g_offmask[((b*27 + o)*HO + ho)*WO + wo] = v;
        }
    }
}

// ---------------------------------------------------------------------------
// Kernel 2: deformable GEMM on tensor cores via mma.sync (bf16 hi/lo, 3-pass)
// One block = one (b, ho): D[128 px][64 o], K = 9 taps x 64 c.
// ---------------------------------------------------------------------------
#define SM_A     0         // A hi 16KB (+lo at +16384): row px (128B, sw128)
#define SM_W     32768     // W double buffer: 2 x (hi 8KB + lo 8KB)
#define SM_META  65536     // 9 taps * 128 px * 32B = 36864 (reused as outbuf)
#define SM_TOTAL 102400

__global__ void __launch_bounds__(256, 2) deform_kernel(const float* __restrict__ x,
                                                        float* __restrict__ out) {
    extern __shared__ char sm[];
    const uint32_t smb = smem_u32(sm);
    int tid = threadIdx.x;
    int l = tid & 31, w = tid >> 5;
    int ho = blockIdx.x, b = blockIdx.y;
    const float* xb = x + (size_t)b * CIN * HW_;

    // ---- meta precompute: all 9 taps x 128 px ----
    for (int t = tid; t < 9*128; t += 256) {
        int tap = t >> 7, px = t & 127;
        const float* om = g_offmask + (size_t)b*27*HO*WO + (size_t)ho*WO + px;
        float offy = om[(size_t)(2*tap)   * (HO*WO)];
        float offx = om[(size_t)(2*tap+1) * (HO*WO)];
        float m    = om[(size_t)(18+tap)  * (HO*WO)];
        float py  = offy + (float)(tap/3) + (float)(2*ho - 1);
        float pxx = offx + (float)(tap%3) + (float)(px - 1);
        float y0f = floorf(py), x0f = floorf(pxx);
        float dy = py - y0f,  dx = pxx - x0f;
        int y0 = (int)y0f, x0 = (int)x0f;
        int y1 = y0 + 1,   x1 = x0 + 1;
        bool vy0 = (y0>=0)&&(y0<H_), vy1 = (y1>=0)&&(y1<H_);
        bool vx0 = (x0>=0)&&(x0<W_), vx1 = (x1>=0)&&(x1<W_);
        float* mp = (float*)(sm + SM_META + t*32);
        mp[0] = (1.f-dy)*(1.f-dx)*m * ((vy0&&vx0)?1.f:0.f);
        mp[1] = (1.f-dy)*dx      *m * ((vy0&&vx1)?1.f:0.f);
        mp[2] = dy*(1.f-dx)      *m * ((vy1&&vx0)?1.f:0.f);
        mp[3] = dy*dx            *m * ((vy1&&vx1)?1.f:0.f);
        int cy0 = min(max(y0,0),H_-1), cy1 = min(max(y1,0),H_-1);
        int cx0 = min(max(x0,0),W_-1), cx1 = min(max(x1,0),W_-1);
        ((int*)mp)[4] = cy0*W_ + cx0;
        ((int*)mp)[5] = cy0*W_ + cx1;
        ((int*)mp)[6] = cy1*W_ + cx0;
        ((int*)mp)[7] = cy1*W_ + cx1;
    }

    // ---- prologue: stage W tap 0 ----
    {
        uint32_t dst = smb + SM_W + tid*16;
        const char* src = g_Wsplit + tid*16;
        #pragma unroll
        for (int j = 0; j < 4; ++j)
            asm volatile("cp.async.cg.shared.global [%0], [%1], 16;"
                         :: "r"(dst + j*4096u), "l"(src + j*4096) : "memory");
        asm volatile("cp.async.commit_group;" ::: "memory");
    }

    // ---- ldmatrix lane address precompute (relative, swizzled) ----
    int px0 = (w & 3) * 32;          // mma px tile base (also gather px range)
    int o0  = (w >> 2) * 32;         // mma o tile base
    int gpx = px0 + l;               // gather: lanes = 32 consecutive px
    int gc0 = (w >> 2) * 32;         // gather channel half

    uint32_t aoff[2][4], boff[2][4];
    {
        int arow = px0 + (l & 15);
        int acol = (l & 16) ? 16 : 0;
        #pragma unroll
        for (int m = 0; m < 2; ++m)
            #pragma unroll
            for (int ks = 0; ks < 4; ++ks)
                aoff[m][ks] = sw128((uint32_t)((arow + m*16)*128 + ks*32 + acol));
        int brow = o0 + (l & 7) + ((l & 16) ? 8 : 0);
        int bcol = (l & 8) ? 16 : 0;
        #pragma unroll
        for (int np = 0; np < 2; ++np)
            #pragma unroll
            for (int ks = 0; ks < 4; ++ks)
                boff[np][ks] = sw128((uint32_t)((brow + np*16)*128 + ks*32 + bcol));
    }

    float acc[2][4][4];
    #pragma unroll
    for (int m = 0; m < 2; ++m)
        #pragma unroll
        for (int nt = 0; nt < 4; ++nt)
            #pragma unroll
            for (int r = 0; r < 4; ++r) acc[m][nt][r] = 0.f;

    __syncthreads();   // meta visible

    #pragma unroll 1
    for (int k = 0; k < 9; ++k) {
        if (k) __syncthreads();      // mma(k-1) done -> A/W reusable

        // ---- gather tap k -> A (hi/lo bf16, sw128) ----
        {
            const char* mp = sm + SM_META + ((k << 7) + gpx)*32;
            float w00 = ((const float*)mp)[0], w01 = ((const float*)mp)[1];
            float w10 = ((const float*)mp)[2], w11 = ((const float*)mp)[3];
            int o00 = ((const int*)mp)[4], o01 = ((const int*)mp)[5];
            int o10 = ((const int*)mp)[6], o11 = ((const int*)mp)[7];
            const float* xc = xb + (size_t)gc0 * HW_;
            char* ahi = sm + SM_A;
            char* alo = sm + SM_A + 16384;
            uint32_t rowoff = (uint32_t)(gpx*128 + gc0*2);
            #pragma unroll
            for (int j = 0; j < 16; ++j) {
                float v0 = w00*__ldg(xc+o00) + w01*__ldg(xc+o01)
                         + w10*__ldg(xc+o10) + w11*__ldg(xc+o11);
                const float* xc1 = xc + HW_;
                float v1 = w00*__ldg(xc1+o00) + w01*__ldg(xc1+o01)
                         + w10*__ldg(xc1+o10) + w11*__ldg(xc1+o11);
                xc += 2*HW_;
                uint32_t h;
                asm("cvt.rn.bf16x2.f32 %0, %1, %2;" : "=r"(h) : "f"(v1), "f"(v0));
                float h0 = __uint_as_float(h << 16);
                float h1 = __uint_as_float(h & 0xffff0000u);
                float l0 = v0 - h0, l1 = v1 - h1;
                uint32_t lw;
                asm("cvt.rn.bf16x2.f32 %0, %1, %2;" : "=r"(lw) : "f"(l1), "f"(l0));
                uint32_t sw = sw128(rowoff + j*4);
                *(uint32_t*)(ahi + sw) = h;
                *(uint32_t*)(alo + sw) = lw;
            }
        }

        if (k < 8) {
            uint32_t dst = smb + SM_W + ((k+1)&1)*16384u + tid*16;
            const char* src = g_Wsplit + (k+1)*16384 + tid*16;
            #pragma unroll
            for (int j = 0; j < 4; ++j)
                asm volatile("cp.async.cg.shared.global [%0], [%1], 16;"
                             :: "r"(dst + j*4096u), "l"(src + j*4096) : "memory");
            asm volatile("cp.async.commit_group;" ::: "memory");
            asm volatile("cp.async.wait_group 1;" ::: "memory");
        } else {
            asm volatile("cp.async.wait_group 0;" ::: "memory");
        }
        __syncthreads();             // A + W[k] ready

        // ---- tensor GEMM: 3 passes ----
        uint32_t wbase = smb + SM_W + (k & 1)*16384u;
        uint32_t bg[4][4][2];
        // B hi
        #pragma unroll
        for (int np = 0; np < 2; ++np)
            #pragma unroll
            for (int ks = 0; ks < 4; ++ks) {
                uint32_t r0,r1,r2,r3;
                LDMATRIX_X4(r0,r1,r2,r3, wbase + boff[np][ks]);
                bg[np*2][ks][0] = r0; bg[np*2][ks][1] = r1;
                bg[np*2+1][ks][0] = r2; bg[np*2+1][ks][1] = r3;
            }
        // pass 1 (Ahi*Bhi) and pass 2 (Alo*Bhi)
        #pragma unroll
        for (int half = 0; half < 2; ++half) {
            uint32_t abase = smb + SM_A + half*16384u;
            #pragma unroll
            for (int m = 0; m < 2; ++m)
                #pragma unroll
                for (int ks = 0; ks < 4; ++ks) {
                    uint32_t a0,a1,a2,a3;
                    LDMATRIX_X4(a0,a1,a2,a3, abase + aoff[m][ks]);
                    #pragma unroll
                    for (int nt = 0; nt < 4; ++nt)
                        MMA_BF16(acc[m][nt], a0,a1,a2,a3, bg[nt][ks][0], bg[nt][ks][1]);
                }
        }
        // B lo
        #pragma unroll
        for (int np = 0; np < 2; ++np)
            #pragma unroll
            for (int ks = 0; ks < 4; ++ks) {
                uint32_t r0,r1,r2,r3;
                LDMATRIX_X4(r0,r1,r2,r3, wbase + 8192u + boff[np][ks]);
                bg[np*2][ks][0] = r0; bg[np*2][ks][1] = r1;
                bg[np*2+1][ks][0] = r2; bg[np*2+1][ks][1] = r3;
            }
        // pass 3 (Ahi*Blo)
        #pragma unroll
        for (int m = 0; m < 2; ++m)
            #pragma unroll
            for (int ks = 0; ks < 4; ++ks) {
                uint32_t a0,a1,a2,a3;
                LDMATRIX_X4(a0,a1,a2,a3, smb + SM_A + aoff[m][ks]);
                #pragma unroll
                for (int nt = 0; nt < 4; ++nt)
                    MMA_BF16(acc[m][nt], a0,a1,a2,a3, bg[nt][ks][0], bg[nt][ks][1]);
            }
    }

    // ---- epilogue: transpose via smem (reuse meta region), coalesced store ----
    __syncthreads();
    float* ob = (float*)(sm + SM_META);   // pitch 132 floats
    int g = l >> 2, tg = l & 3;
    #pragma unroll
    for (int m = 0; m < 2; ++m)
        #pragma unroll
        for (int nt = 0; nt < 4; ++nt) {
            int o  = o0 + nt*8 + 2*tg;
            int pa = px0 + m*16 + g;
            ob[o*132 + pa]         = acc[m][nt][0];
            ob[(o+1)*132 + pa]     = acc[m][nt][1];
            ob[o*132 + pa + 8]     = acc[m][nt][2];
            ob[(o+1)*132 + pa + 8] = acc[m][nt][3];
        }
    __syncthreads();
    for (int i = tid; i < 64*32; i += 256) {
        int o = i >> 5, seg = i & 31;
        float4 v = *(float4*)&ob[o*132 + seg*4];
        *(float4*)&out[(((size_t)b*CO + o)*HO + ho)*WO + seg*4] = v;
    }
}

// ---------------------------------------------------------------------------
extern "C" void kernel_launch(void* const* d_in, const int* in_sizes, int n_in,
                              void* d_out, int out_size) {
    const float* x      = (const float*)d_in[0];
    const float* w_off  = (const float*)d_in[1];
    const float* b_off  = (const float*)d_in[2];
    const float* w_mask = (const float*)d_in[3];
    const float* b_mask = (const float*)d_in[4];
    const float* w_conv = (const float*)d_in[5];
    float* out = (float*)d_out;

    prep_kernel<<<144, 256>>>(w_off, b_off, w_mask, b_mask, w_conv);

    int smem1 = (6528 + 18432) * (int)sizeof(float);   // 99,840 B
    cudaFuncSetAttribute((const void*)conv_om_kernel,
                         cudaFuncAttributeMaxDynamicSharedMemorySize, smem1);
    conv_om_kernel<<<dim3(4, 64, 8), 256, smem1>>>(x);

    cudaFuncSetAttribute((const void*)deform_kernel,
                         cudaFuncAttributeMaxDynamicSharedMemorySize, SM_TOTAL);
    deform_kernel<<<dim3(HO, B_), 256, SM_TOTAL>>>(x, out);
}

// round 6
// speedup vs baseline: 2.8100x; 1.5466x over previous
#include <cuda_runtime.h>
#include <cuda_bf16.h>
#include <math.h>
#include <stdint.h>

#define B_  8
#define CIN 64
#define H_  128
#define W_  128
#define HO  64
#define WO  128
#define CO  64
#define HW_ (H_*W_)

// Scratch (no allocations allowed -> __device__ globals)
__device__ float g_bias[32];
// Deform GEMM weights, per tap k: 8KB hi + 8KB lo; rows = o (64), cols = c (128B bf16), SW128.
__device__ __align__(16) char g_Wsplit[9*16384];
// Offset/mask conv weights, per tap k: 4KB hi + 4KB lo; rows = o (32), cols = c (128B bf16), SW128.
__device__ __align__(16) char g_WomSplit[9*8192];

__device__ __forceinline__ uint32_t smem_u32(const void* p) {
    uint32_t a;
    asm("{ .reg .u64 t; cvta.to.shared.u64 t, %1; cvt.u32.u64 %0, t; }" : "=r"(a) : "l"(p));
    return a;
}
__device__ __forceinline__ uint32_t sw128(uint32_t off) { return off ^ ((off >> 3) & 0x70); }

#define LDMATRIX_X4(r0,r1,r2,r3,addr) \
    asm volatile("ldmatrix.sync.aligned.m8n8.x4.shared.b16 {%0,%1,%2,%3}, [%4];" \
                 : "=r"(r0),"=r"(r1),"=r"(r2),"=r"(r3) : "r"(addr))

#define MMA_BF16(c, a0,a1,a2,a3, b0,b1) \
    asm volatile("mma.sync.aligned.m16n8k16.row.col.f32.bf16.bf16.f32 " \
                 "{%0,%1,%2,%3},{%4,%5,%6,%7},{%8,%9},{%0,%1,%2,%3};" \
                 : "+f"((c)[0]),"+f"((c)[1]),"+f"((c)[2]),"+f"((c)[3]) \
                 : "r"(a0),"r"(a1),"r"(a2),"r"(a3), "r"(b0),"r"(b1))

#define CP16(dst, src) \
    asm volatile("cp.async.cg.shared.global [%0], [%1], 16;" :: "r"(dst), "l"(src) : "memory")
#define CP_COMMIT() asm volatile("cp.async.commit_group;" ::: "memory")
#define CP_WAIT(n)  asm volatile("cp.async.wait_group %0;" :: "n"(n) : "memory")

// ---------------------------------------------------------------------------
// Kernel 0: weight repack (hi/lo split, SW128 swizzled)
// ---------------------------------------------------------------------------
__global__ void prep_kernel(const float* __restrict__ w_off, const float* __restrict__ b_off,
                            const float* __restrict__ w_mask, const float* __restrict__ b_mask,
                            const float* __restrict__ w_conv) {
    int idx = blockIdx.x * blockDim.x + threadIdx.x;
    if (idx < 9*64*64) {
        int k = idx / 4096; int r = idx & 4095; int o = r >> 6; int c = r & 63;
        float w = w_conv[(o*64 + c)*9 + k];
        __nv_bfloat16 hi = __float2bfloat16(w);
        __nv_bfloat16 lo = __float2bfloat16(w - __bfloat162float(hi));
        uint32_t sw = sw128((uint32_t)(o*128 + c*2));
        *(__nv_bfloat16*)(g_Wsplit + k*16384 + sw)        = hi;
        *(__nv_bfloat16*)(g_Wsplit + k*16384 + 8192 + sw) = lo;
    }
    if (idx < 9*32*64) {
        int k = idx / 2048; int r = idx & 2047; int o = r >> 6; int c = r & 63;
        float w = 0.f;
        if (o < 18)       w = w_off[(o*64 + c)*9 + k];
        else if (o < 27)  w = w_mask[((o-18)*64 + c)*9 + k];
        __nv_bfloat16 hi = __float2bfloat16(w);
        __nv_bfloat16 lo = __float2bfloat16(w - __bfloat162float(hi));
        uint32_t sw = sw128((uint32_t)(o*128 + c*2));
        *(__nv_bfloat16*)(g_WomSplit + k*8192 + sw)        = hi;
        *(__nv_bfloat16*)(g_WomSplit + k*8192 + 4096 + sw) = lo;
    }
    if (idx < 32) {
        float v = 0.f;
        if (idx < 18)      v = b_off[idx];
        else if (idx < 27) v = b_mask[idx - 18];
        g_bias[idx] = v;
    }
}

// ---------------------------------------------------------------------------
// Fused kernel: phase 1 = offset/mask conv (tensor), phase 2 = gather + GEMM.
// One block = one (b, ho): D[128 px][64 o].
// ---------------------------------------------------------------------------
#define SM_A     0          // A hi 16KB + lo 16KB: row px (128B, sw128)
#define SM_WD    32768      // deform W double buffer: 2 x (hi 8KB + lo 8KB)
#define SM_WOM   65536      // conv W double buffer: 2 x (hi 4KB + lo 4KB)
#define SM_SOM   81920      // som[128 px][33 floats]  (27 valid o) = 16,896B
#define SM_META  99328      // meta double buffer: 2 x 128px x 32B
#define SM_TOTAL 107520     // -> 2 CTAs/SM

__global__ void __launch_bounds__(256, 2) deform_kernel(const float* __restrict__ x,
                                                        float* __restrict__ out) {
    extern __shared__ char sm[];
    const uint32_t smb = smem_u32(sm);
    int tid = threadIdx.x;
    int l = tid & 31, w = tid >> 5;
    int ho = blockIdx.x, b = blockIdx.y;
    const float* xb = x + (size_t)b * CIN * HW_;

    int px0 = (w & 3) * 32;          // px tile base (gather + mma rows)
    int o0  = (w >> 2) * 32;         // phase-2 o tile base / gather channel half
    int oh  = (w >> 2) * 16;         // phase-1 o tile base (N=32 split across 2 warp groups)
    int gpx = px0 + l;

    // ---- ldmatrix lane offsets (relative, swizzled) ----
    uint32_t aoff[2][4], boff[2][4], b1off[4];
    {
        int arow = px0 + (l & 15);
        int acol = (l & 16) ? 16 : 0;
        #pragma unroll
        for (int m = 0; m < 2; ++m)
            #pragma unroll
            for (int ks = 0; ks < 4; ++ks)
                aoff[m][ks] = sw128((uint32_t)((arow + m*16)*128 + ks*32 + acol));
        int brow = o0 + (l & 7) + ((l & 16) ? 8 : 0);
        int bcol = (l & 8) ? 16 : 0;
        #pragma unroll
        for (int np = 0; np < 2; ++np)
            #pragma unroll
            for (int ks = 0; ks < 4; ++ks)
                boff[np][ks] = sw128((uint32_t)((brow + np*16)*128 + ks*32 + bcol));
        int b1row = oh + (l & 7) + ((l & 16) ? 8 : 0);
        #pragma unroll
        for (int ks = 0; ks < 4; ++ks)
            b1off[ks] = sw128((uint32_t)(b1row*128 + ks*32 + bcol));
    }

    // ================= PHASE 1: offset/mask conv =================
    // stage Wom tap 0
    {
        uint32_t dst = smb + SM_WOM + tid*16;
        const char* src = g_WomSplit + tid*16;
        CP16(dst, src); CP16(dst + 4096u, src + 4096);
        CP_COMMIT();
    }

    float acc1[2][2][4];
    #pragma unroll
    for (int m = 0; m < 2; ++m)
        #pragma unroll
        for (int nt = 0; nt < 2; ++nt)
            #pragma unroll
            for (int r = 0; r < 4; ++r) acc1[m][nt][r] = 0.f;

    #pragma unroll 1
    for (int k = 0; k < 9; ++k) {
        if (k) __syncthreads();

        // build A_k[px][c]: plain strided loads (im2col row), hi/lo bf16, sw128
        {
            int gy = 2*ho - 1 + (k/3);
            int gx = gpx - 1 + (k%3);
            bool vld = (gy >= 0) && (gx >= 0) && (gx < W_);   // gy < 128 always
            char* ahi = sm + SM_A;
            char* alo = sm + SM_A + 16384;
            uint32_t rowoff = (uint32_t)(gpx*128 + o0*2);
            const float* xc = xb + (size_t)o0 * HW_ + gy*W_ + gx;
            #pragma unroll
            for (int j = 0; j < 16; ++j) {
                float v0 = vld ? __ldg(xc)       : 0.f;
                float v1 = vld ? __ldg(xc + HW_) : 0.f;
                xc += 2*HW_;
                uint32_t h;
                asm("cvt.rn.bf16x2.f32 %0, %1, %2;" : "=r"(h) : "f"(v1), "f"(v0));
                float h0 = __uint_as_float(h << 16);
                float h1 = __uint_as_float(h & 0xffff0000u);
                uint32_t lw;
                { float l0 = v0 - h0, l1 = v1 - h1;
                  asm("cvt.rn.bf16x2.f32 %0, %1, %2;" : "=r"(lw) : "f"(l1), "f"(l0)); }
                uint32_t sw = sw128(rowoff + j*4);
                *(uint32_t*)(ahi + sw) = h;
                *(uint32_t*)(alo + sw) = lw;
            }
        }
        if (k < 8) {
            uint32_t dst = smb + SM_WOM + ((k+1)&1)*8192u + tid*16;
            const char* src = g_WomSplit + (k+1)*8192 + tid*16;
            CP16(dst, src); CP16(dst + 4096u, src + 4096);
            CP_COMMIT();
            CP_WAIT(1);
        } else {
            CP_WAIT(0);
        }
        __syncthreads();

        uint32_t wbase = smb + SM_WOM + (k & 1)*8192u;
        uint32_t bg[2][4][2];
        #pragma unroll
        for (int ks = 0; ks < 4; ++ks) {
            uint32_t r0,r1,r2,r3;
            LDMATRIX_X4(r0,r1,r2,r3, wbase + b1off[ks]);
            bg[0][ks][0]=r0; bg[0][ks][1]=r1; bg[1][ks][0]=r2; bg[1][ks][1]=r3;
        }
        #pragma unroll
        for (int half = 0; half < 2; ++half) {
            uint32_t abase = smb + SM_A + half*16384u;
            #pragma unroll
            for (int m = 0; m < 2; ++m)
                #pragma unroll
                for (int ks = 0; ks < 4; ++ks) {
                    uint32_t a0,a1,a2,a3;
                    LDMATRIX_X4(a0,a1,a2,a3, abase + aoff[m][ks]);
                    #pragma unroll
                    for (int nt = 0; nt < 2; ++nt)
                        MMA_BF16(acc1[m][nt], a0,a1,a2,a3, bg[nt][ks][0], bg[nt][ks][1]);
                }
        }
        #pragma unroll
        for (int ks = 0; ks < 4; ++ks) {
            uint32_t r0,r1,r2,r3;
            LDMATRIX_X4(r0,r1,r2,r3, wbase + 4096u + b1off[ks]);
            bg[0][ks][0]=r0; bg[0][ks][1]=r1; bg[1][ks][0]=r2; bg[1][ks][1]=r3;
        }
        #pragma unroll
        for (int m = 0; m < 2; ++m)
            #pragma unroll
            for (int ks = 0; ks < 4; ++ks) {
                uint32_t a0,a1,a2,a3;
                LDMATRIX_X4(a0,a1,a2,a3, smb + SM_A + aoff[m][ks]);
                #pragma unroll
                for (int nt = 0; nt < 2; ++nt)
                    MMA_BF16(acc1[m][nt], a0,a1,a2,a3, bg[nt][ks][0], bg[nt][ks][1]);
            }
    }

    // write som[px][o] = acc + bias (fragment scatter; som untouched so far)
    {
        float* som = (float*)(sm + SM_SOM);
        int g = l >> 2, tg = l & 3;
        #pragma unroll
        for (int m = 0; m < 2; ++m)
            #pragma unroll
            for (int nt = 0; nt < 2; ++nt) {
                int o  = oh + nt*8 + 2*tg;
                int pa = px0 + m*16 + g;
                som[pa*33 + o]       = acc1[m][nt][0] + g_bias[o];
                som[pa*33 + o + 1]   = acc1[m][nt][1] + g_bias[o+1];
                som[(pa+8)*33 + o]   = acc1[m][nt][2] + g_bias[o];
                som[(pa+8)*33 + o+1] = acc1[m][nt][3] + g_bias[o+1];
            }
    }
    // stage deform W tap 0
    {
        uint32_t dst = smb + SM_WD + tid*16;
        const char* src = g_Wsplit + tid*16;
        #pragma unroll
        for (int j = 0; j < 4; ++j) CP16(dst + j*4096u, src + j*4096);
        CP_COMMIT();
    }
    __syncthreads();   // som visible

    // ================= PHASE 2: gather + deform GEMM =================
    // meta for tap 0
    #define META_FROM_SOM(TAP, BUF) do { \
        if (tid < 128) { \
            int px = tid; \
            const float* som = (const float*)(sm + SM_SOM); \
            float offy = som[px*33 + 2*(TAP)]; \
            float offx = som[px*33 + 2*(TAP) + 1]; \
            float mr   = som[px*33 + 18 + (TAP)]; \
            float mk   = 1.f / (1.f + expf(-mr)); \
            float py  = offy + (float)((TAP)/3) + (float)(2*ho - 1); \
            float pxx = offx + (float)((TAP)%3) + (float)(px - 1); \
            float y0f = floorf(py), x0f = floorf(pxx); \
            float dy = py - y0f,  dx = pxx - x0f; \
            int y0 = (int)y0f, x0 = (int)x0f; \
            int y1 = y0 + 1,   x1 = x0 + 1; \
            bool vy0 = (y0>=0)&&(y0<H_), vy1 = (y1>=0)&&(y1<H_); \
            bool vx0 = (x0>=0)&&(x0<W_), vx1 = (x1>=0)&&(x1<W_); \
            float* mp = (float*)(sm + SM_META + (BUF)*4096 + px*32); \
            mp[0] = (1.f-dy)*(1.f-dx)*mk * ((vy0&&vx0)?1.f:0.f); \
            mp[1] = (1.f-dy)*dx      *mk * ((vy0&&vx1)?1.f:0.f); \
            mp[2] = dy*(1.f-dx)      *mk * ((vy1&&vx0)?1.f:0.f); \
            mp[3] = dy*dx            *mk * ((vy1&&vx1)?1.f:0.f); \
            int cy0 = min(max(y0,0),H_-1), cy1 = min(max(y1,0),H_-1); \
            int cx0 = min(max(x0,0),W_-1), cx1 = min(max(x1,0),W_-1); \
            ((int*)mp)[4] = cy0*W_ + cx0; \
            ((int*)mp)[5] = cy0*W_ + cx1; \
            ((int*)mp)[6] = cy1*W_ + cx0; \
            ((int*)mp)[7] = cy1*W_ + cx1; \
        } \
    } while (0)

    META_FROM_SOM(0, 0);
    __syncthreads();

    float acc[2][4][4];
    #pragma unroll
    for (int m = 0; m < 2; ++m)
        #pragma unroll
        for (int nt = 0; nt < 4; ++nt)
            #pragma unroll
            for (int r = 0; r < 4; ++r) acc[m][nt][r] = 0.f;

    #pragma unroll 1
    for (int k = 0; k < 9; ++k) {
        if (k) __syncthreads();

        // gather tap k -> A (hi/lo bf16, sw128)
        {
            const char* mp = sm + SM_META + (k & 1)*4096 + gpx*32;
            float w00 = ((const float*)mp)[0], w01 = ((const float*)mp)[1];
            float w10 = ((const float*)mp)[2], w11 = ((const float*)mp)[3];
            int o00 = ((const int*)mp)[4], o01 = ((const int*)mp)[5];
            int o10 = ((const int*)mp)[6], o11 = ((const int*)mp)[7];
            const float* xc = xb + (size_t)o0 * HW_;
            char* ahi = sm + SM_A;
            char* alo = sm + SM_A + 16384;
            uint32_t rowoff = (uint32_t)(gpx*128 + o0*2);
            #pragma unroll
            for (int j = 0; j < 16; ++j) {
                float v0 = w00*__ldg(xc+o00) + w01*__ldg(xc+o01)
                         + w10*__ldg(xc+o10) + w11*__ldg(xc+o11);
                const float* xc1 = xc + HW_;
                float v1 = w00*__ldg(xc1+o00) + w01*__ldg(xc1+o01)
                         + w10*__ldg(xc1+o10) + w11*__ldg(xc1+o11);
                xc += 2*HW_;
                uint32_t h;
                asm("cvt.rn.bf16x2.f32 %0, %1, %2;" : "=r"(h) : "f"(v1), "f"(v0));
                float h0 = __uint_as_float(h << 16);
                float h1 = __uint_as_float(h & 0xffff0000u);
                uint32_t lw;
                { float l0 = v0 - h0, l1 = v1 - h1;
                  asm("cvt.rn.bf16x2.f32 %0, %1, %2;" : "=r"(lw) : "f"(l1), "f"(l0)); }
                uint32_t sw = sw128(rowoff + j*4);
                *(uint32_t*)(ahi + sw) = h;
                *(uint32_t*)(alo + sw) = lw;
            }
        }
        if (k < 8) META_FROM_SOM(k+1, (k+1)&1);

        if (k < 8) {
            uint32_t dst = smb + SM_WD + ((k+1)&1)*16384u + tid*16;
            const char* src = g_Wsplit + (k+1)*16384 + tid*16;
            #pragma unroll
            for (int j = 0; j < 4; ++j) CP16(dst + j*4096u, src + j*4096);
            CP_COMMIT();
            CP_WAIT(1);
        } else {
            CP_WAIT(0);
        }
        __syncthreads();

        // tensor GEMM: 3 passes
        uint32_t wbase = smb + SM_WD + (k & 1)*16384u;
        uint32_t bg[4][4][2];
        #pragma unroll
        for (int np = 0; np < 2; ++np)
            #pragma unroll
            for (int ks = 0; ks < 4; ++ks) {
                uint32_t r0,r1,r2,r3;
                LDMATRIX_X4(r0,r1,r2,r3, wbase + boff[np][ks]);
                bg[np*2][ks][0]=r0; bg[np*2][ks][1]=r1;
                bg[np*2+1][ks][0]=r2; bg[np*2+1][ks][1]=r3;
            }
        #pragma unroll
        for (int half = 0; half < 2; ++half) {
            uint32_t abase = smb + SM_A + half*16384u;
            #pragma unroll
            for (int m = 0; m < 2; ++m)
                #pragma unroll
                for (int ks = 0; ks < 4; ++ks) {
                    uint32_t a0,a1,a2,a3;
                    LDMATRIX_X4(a0,a1,a2,a3, abase + aoff[m][ks]);
                    #pragma unroll
                    for (int nt = 0; nt < 4; ++nt)
                        MMA_BF16(acc[m][nt], a0,a1,a2,a3, bg[nt][ks][0], bg[nt][ks][1]);
                }
        }
        #pragma unroll
        for (int np = 0; np < 2; ++np)
            #pragma unroll
            for (int ks = 0; ks < 4; ++ks) {
                uint32_t r0,r1,r2,r3;
                LDMATRIX_X4(r0,r1,r2,r3, wbase + 8192u + boff[np][ks]);
                bg[np*2][ks][0]=r0; bg[np*2][ks][1]=r1;
                bg[np*2+1][ks][0]=r2; bg[np*2+1][ks][1]=r3;
            }
        #pragma unroll
        for (int m = 0; m < 2; ++m)
            #pragma unroll
            for (int ks = 0; ks < 4; ++ks) {
                uint32_t a0,a1,a2,a3;
                LDMATRIX_X4(a0,a1,a2,a3, smb + SM_A + aoff[m][ks]);
                #pragma unroll
                for (int nt = 0; nt < 4; ++nt)
                    MMA_BF16(acc[m][nt], a0,a1,a2,a3, bg[nt][ks][0], bg[nt][ks][1]);
            }
    }

    // ---- epilogue: transpose via smem (reuse WD+WOM region), coalesced store ----
    __syncthreads();
    float* ob = (float*)(sm + SM_WD);   // pitch 132 floats, 64*132*4 = 33,792B fits WD+WOM
    int g = l >> 2, tg = l & 3;
    #pragma unroll
    for (int m = 0; m < 2; ++m)
        #pragma unroll
        for (int nt = 0; nt < 4; ++nt) {
            int o  = o0 + nt*8 + 2*tg;
            int pa = px0 + m*16 + g;
            ob[o*132 + pa]         = acc[m][nt][0];
            ob[(o+1)*132 + pa]     = acc[m][nt][1];
            ob[o*132 + pa + 8]     = acc[m][nt][2];
            ob[(o+1)*132 + pa + 8] = acc[m][nt][3];
        }
    __syncthreads();
    for (int i = tid; i < 64*32; i += 256) {
        int o = i >> 5, seg = i & 31;
        float4 v = *(float4*)&ob[o*132 + seg*4];
        *(float4*)&out[(((size_t)b*CO + o)*HO + ho)*WO + seg*4] = v;
    }
}

// ---------------------------------------------------------------------------
extern "C" void kernel_launch(void* const* d_in, const int* in_sizes, int n_in,
                              void* d_out, int out_size) {
    const float* x      = (const float*)d_in[0];
    const float* w_off  = (const float*)d_in[1];
    const float* b_off  = (const float*)d_in[2];
    const float* w_mask = (const float*)d_in[3];
    const float* b_mask = (const float*)d_in[4];
    const float* w_conv = (const float*)d_in[5];
    float* out = (float*)d_out;

    prep_kernel<<<144, 256>>>(w_off, b_off, w_mask, b_mask, w_conv);

    cudaFuncSetAttribute((const void*)deform_kernel,
                         cudaFuncAttributeMaxDynamicSharedMemorySize, SM_TOTAL);
    deform_kernel<<<dim3(HO, B_), 256, SM_TOTAL>>>(x, out);
}

// round 7
// speedup vs baseline: 3.1691x; 1.1278x over previous
#include <cuda_runtime.h>
#include <cuda_bf16.h>
#include <math.h>
#include <stdint.h>

#define B_  8
#define CIN 64
#define H_  128
#define W_  128
#define HO  64
#define WO  128
#define CO  64
#define HW_ (H_*W_)

// Scratch (no allocations allowed -> __device__ globals)
__device__ float g_bias[32];
__device__ __align__(16) char g_Wsplit[9*16384];   // deform W: per tap hi 8KB + lo 8KB, SW128
__device__ __align__(16) char g_WomSplit[9*8192];  // conv W: per tap hi 4KB + lo 4KB, SW128

__device__ __forceinline__ uint32_t smem_u32(const void* p) {
    uint32_t a;
    asm("{ .reg .u64 t; cvta.to.shared.u64 t, %1; cvt.u32.u64 %0, t; }" : "=r"(a) : "l"(p));
    return a;
}
__device__ __forceinline__ uint32_t sw128(uint32_t off) { return off ^ ((off >> 3) & 0x70); }

#define LDMATRIX_X4(r0,r1,r2,r3,addr) \
    asm volatile("ldmatrix.sync.aligned.m8n8.x4.shared.b16 {%0,%1,%2,%3}, [%4];" \
                 : "=r"(r0),"=r"(r1),"=r"(r2),"=r"(r3) : "r"(addr))

#define MMA_BF16(c, a0,a1,a2,a3, b0,b1) \
    asm volatile("mma.sync.aligned.m16n8k16.row.col.f32.bf16.bf16.f32 " \
                 "{%0,%1,%2,%3},{%4,%5,%6,%7},{%8,%9},{%0,%1,%2,%3};" \
                 : "+f"((c)[0]),"+f"((c)[1]),"+f"((c)[2]),"+f"((c)[3]) \
                 : "r"(a0),"r"(a1),"r"(a2),"r"(a3), "r"(b0),"r"(b1))

#define CP16(dst, src) \
    asm volatile("cp.async.cg.shared.global [%0], [%1], 16;" :: "r"(dst), "l"(src) : "memory")
#define CP_COMMIT() asm volatile("cp.async.commit_group;" ::: "memory")
#define CP_WAIT(n)  asm volatile("cp.async.wait_group %0;" :: "n"(n) : "memory")

// bf16 hi/lo split of (v0, v1) -> packed hi word + packed lo word
#define SPLIT2(v0, v1, h, lw) do { \
    asm("cvt.rn.bf16x2.f32 %0, %1, %2;" : "=r"(h) : "f"(v1), "f"(v0)); \
    float _h0 = __uint_as_float((h) << 16); \
    float _h1 = __uint_as_float((h) & 0xffff0000u); \
    float _l0 = (v0) - _h0, _l1 = (v1) - _h1; \
    asm("cvt.rn.bf16x2.f32 %0, %1, %2;" : "=r"(lw) : "f"(_l1), "f"(_l0)); \
} while (0)

// ---------------------------------------------------------------------------
// Kernel 0: weight repack (hi/lo split, SW128 swizzled)
// ---------------------------------------------------------------------------
__global__ void prep_kernel(const float* __restrict__ w_off, const float* __restrict__ b_off,
                            const float* __restrict__ w_mask, const float* __restrict__ b_mask,
                            const float* __restrict__ w_conv) {
    int idx = blockIdx.x * blockDim.x + threadIdx.x;
    if (idx < 9*64*64) {
        int k = idx / 4096; int r = idx & 4095; int o = r >> 6; int c = r & 63;
        float w = w_conv[(o*64 + c)*9 + k];
        __nv_bfloat16 hi = __float2bfloat16(w);
        __nv_bfloat16 lo = __float2bfloat16(w - __bfloat162float(hi));
        uint32_t sw = sw128((uint32_t)(o*128 + c*2));
        *(__nv_bfloat16*)(g_Wsplit + k*16384 + sw)        = hi;
        *(__nv_bfloat16*)(g_Wsplit + k*16384 + 8192 + sw) = lo;
    }
    if (idx < 9*32*64) {
        int k = idx / 2048; int r = idx & 2047; int o = r >> 6; int c = r & 63;
        float w = 0.f;
        if (o < 18)       w = w_off[(o*64 + c)*9 + k];
        else if (o < 27)  w = w_mask[((o-18)*64 + c)*9 + k];
        __nv_bfloat16 hi = __float2bfloat16(w);
        __nv_bfloat16 lo = __float2bfloat16(w - __bfloat162float(hi));
        uint32_t sw = sw128((uint32_t)(o*128 + c*2));
        *(__nv_bfloat16*)(g_WomSplit + k*8192 + sw)        = hi;
        *(__nv_bfloat16*)(g_WomSplit + k*8192 + 4096 + sw) = lo;
    }
    if (idx < 32) {
        float v = 0.f;
        if (idx < 18)      v = b_off[idx];
        else if (idx < 27) v = b_mask[idx - 18];
        g_bias[idx] = v;
    }
}

// ---------------------------------------------------------------------------
// Fused kernel: phase 1 = offset/mask conv (tensor), phase 2 = gather + GEMM.
// One block = one (b, ho): D[128 px][64 o].
// ---------------------------------------------------------------------------
#define SM_A     0          // A hi 16KB + lo 16KB: row px (128B, sw128)
#define SM_WD    32768      // deform W double buffer: 2 x (hi 8KB + lo 8KB)
#define SM_WOM   65536      // conv W double buffer: 2 x (hi 4KB + lo 4KB)
#define SM_SOM   81920      // som[128 px][33 floats]
#define SM_META  99328      // meta double buffer: 2 x 128px x 32B
#define SM_TOTAL 107520     // -> 2 CTAs/SM

__global__ void __launch_bounds__(256, 2) deform_kernel(const float* __restrict__ x,
                                                        float* __restrict__ out) {
    extern __shared__ char sm[];
    const uint32_t smb = smem_u32(sm);
    int tid = threadIdx.x;
    int l = tid & 31, w = tid >> 5;
    int ho = blockIdx.x, b = blockIdx.y;
    const float* xb = x + (size_t)b * CIN * HW_;

    int px0 = (w & 3) * 32;          // px tile base (gather + mma rows)
    int o0  = (w >> 2) * 32;         // phase-2 o tile base / gather channel half
    int oh  = (w >> 2) * 16;         // phase-1 o tile base
    int gpx = px0 + l;

    // ---- ldmatrix lane offsets (relative, swizzled) ----
    uint32_t aoff[2][4], boff[2][4], b1off[4];
    {
        int arow = px0 + (l & 15);
        int acol = (l & 16) ? 16 : 0;
        #pragma unroll
        for (int m = 0; m < 2; ++m)
            #pragma unroll
            for (int ks = 0; ks < 4; ++ks)
                aoff[m][ks] = sw128((uint32_t)((arow + m*16)*128 + ks*32 + acol));
        int brow = o0 + (l & 7) + ((l & 16) ? 8 : 0);
        int bcol = (l & 8) ? 16 : 0;
        #pragma unroll
        for (int np = 0; np < 2; ++np)
            #pragma unroll
            for (int ks = 0; ks < 4; ++ks)
                boff[np][ks] = sw128((uint32_t)((brow + np*16)*128 + ks*32 + bcol));
        int b1row = oh + (l & 7) + ((l & 16) ? 8 : 0);
        #pragma unroll
        for (int ks = 0; ks < 4; ++ks)
            b1off[ks] = sw128((uint32_t)(b1row*128 + ks*32 + bcol));
    }

    // ================= PHASE 1: offset/mask conv =================
    {
        uint32_t dst = smb + SM_WOM + tid*16;
        const char* src = g_WomSplit + tid*16;
        CP16(dst, src); CP16(dst + 4096u, src + 4096);
        CP_COMMIT();
    }

    float acc1[2][2][4];
    #pragma unroll
    for (int m = 0; m < 2; ++m)
        #pragma unroll
        for (int nt = 0; nt < 2; ++nt)
            #pragma unroll
            for (int r = 0; r < 4; ++r) acc1[m][nt][r] = 0.f;

    #pragma unroll 1
    for (int k = 0; k < 9; ++k) {
        if (k) __syncthreads();

        // build A_k[px][c]: im2col row loads, hi/lo bf16, sw128, STS.128-batched
        {
            int gy = 2*ho - 1 + (k/3);
            int gx = gpx - 1 + (k%3);
            bool vld = (gy >= 0) && (gx >= 0) && (gx < W_);
            char* ahi = sm + SM_A;
            char* alo = sm + SM_A + 16384;
            uint32_t rowoff = (uint32_t)(gpx*128 + o0*2);
            const float* xc = xb + (size_t)o0 * HW_ + gy*W_ + gx;
            #pragma unroll
            for (int j4 = 0; j4 < 4; ++j4) {
                uint32_t hv[4], lv[4];
                #pragma unroll
                for (int jj = 0; jj < 4; ++jj) {
                    float v0 = vld ? __ldg(xc)       : 0.f;
                    float v1 = vld ? __ldg(xc + HW_) : 0.f;
                    xc += 2*HW_;
                    SPLIT2(v0, v1, hv[jj], lv[jj]);
                }
                uint32_t sw = sw128(rowoff + j4*16);
                *(uint4*)(ahi + sw) = make_uint4(hv[0],hv[1],hv[2],hv[3]);
                *(uint4*)(alo + sw) = make_uint4(lv[0],lv[1],lv[2],lv[3]);
            }
        }
        if (k < 8) {
            uint32_t dst = smb + SM_WOM + ((k+1)&1)*8192u + tid*16;
            const char* src = g_WomSplit + (k+1)*8192 + tid*16;
            CP16(dst, src); CP16(dst + 4096u, src + 4096);
            CP_COMMIT();
            CP_WAIT(1);
        } else {
            CP_WAIT(0);
        }
        __syncthreads();

        uint32_t wbase = smb + SM_WOM + (k & 1)*8192u;
        #pragma unroll
        for (int ks = 0; ks < 4; ++ks) {
            uint32_t ah[2][4], al[2][4], bh[4], bl[4];
            LDMATRIX_X4(ah[0][0],ah[0][1],ah[0][2],ah[0][3], smb + SM_A + aoff[0][ks]);
            LDMATRIX_X4(ah[1][0],ah[1][1],ah[1][2],ah[1][3], smb + SM_A + aoff[1][ks]);
            LDMATRIX_X4(al[0][0],al[0][1],al[0][2],al[0][3], smb + SM_A + 16384u + aoff[0][ks]);
            LDMATRIX_X4(al[1][0],al[1][1],al[1][2],al[1][3], smb + SM_A + 16384u + aoff[1][ks]);
            LDMATRIX_X4(bh[0],bh[1],bh[2],bh[3], wbase + b1off[ks]);
            LDMATRIX_X4(bl[0],bl[1],bl[2],bl[3], wbase + 4096u + b1off[ks]);
            #pragma unroll
            for (int m = 0; m < 2; ++m)
                #pragma unroll
                for (int nt = 0; nt < 2; ++nt) {
                    MMA_BF16(acc1[m][nt], ah[m][0],ah[m][1],ah[m][2],ah[m][3], bh[nt*2], bh[nt*2+1]);
                    MMA_BF16(acc1[m][nt], al[m][0],al[m][1],al[m][2],al[m][3], bh[nt*2], bh[nt*2+1]);
                    MMA_BF16(acc1[m][nt], ah[m][0],ah[m][1],ah[m][2],ah[m][3], bl[nt*2], bl[nt*2+1]);
                }
        }
    }

    // write som[px][o] = acc + bias
    {
        float* som = (float*)(sm + SM_SOM);
        int g = l >> 2, tg = l & 3;
        #pragma unroll
        for (int m = 0; m < 2; ++m)
            #pragma unroll
            for (int nt = 0; nt < 2; ++nt) {
                int o  = oh + nt*8 + 2*tg;
                int pa = px0 + m*16 + g;
                som[pa*33 + o]       = acc1[m][nt][0] + g_bias[o];
                som[pa*33 + o + 1]   = acc1[m][nt][1] + g_bias[o+1];
                som[(pa+8)*33 + o]   = acc1[m][nt][2] + g_bias[o];
                som[(pa+8)*33 + o+1] = acc1[m][nt][3] + g_bias[o+1];
            }
    }
    // stage deform W tap 0
    {
        uint32_t dst = smb + SM_WD + tid*16;
        const char* src = g_Wsplit + tid*16;
        #pragma unroll
        for (int j = 0; j < 4; ++j) CP16(dst + j*4096u, src + j*4096);
        CP_COMMIT();
    }
    __syncthreads();   // som visible

    // ================= PHASE 2: gather + deform GEMM =================
    #define META_FROM_SOM(TAP, BUF) do { \
        if (tid < 128) { \
            int px = tid; \
            const float* som = (const float*)(sm + SM_SOM); \
            float offy = som[px*33 + 2*(TAP)]; \
            float offx = som[px*33 + 2*(TAP) + 1]; \
            float mr   = som[px*33 + 18 + (TAP)]; \
            float mk   = 1.f / (1.f + expf(-mr)); \
            float py  = offy + (float)((TAP)/3) + (float)(2*ho - 1); \
            float pxx = offx + (float)((TAP)%3) + (float)(px - 1); \
            float y0f = floorf(py), x0f = floorf(pxx); \
            float dy = py - y0f,  dx = pxx - x0f; \
            int y0 = (int)y0f, x0 = (int)x0f; \
            int y1 = y0 + 1,   x1 = x0 + 1; \
            bool vy0 = (y0>=0)&&(y0<H_), vy1 = (y1>=0)&&(y1<H_); \
            bool vx0 = (x0>=0)&&(x0<W_), vx1 = (x1>=0)&&(x1<W_); \
            float* mp = (float*)(sm + SM_META + (BUF)*4096 + px*32); \
            mp[0] = (1.f-dy)*(1.f-dx)*mk * ((vy0&&vx0)?1.f:0.f); \
            mp[1] = (1.f-dy)*dx      *mk * ((vy0&&vx1)?1.f:0.f); \
            mp[2] = dy*(1.f-dx)      *mk * ((vy1&&vx0)?1.f:0.f); \
            mp[3] = dy*dx            *mk * ((vy1&&vx1)?1.f:0.f); \
            int cy0 = min(max(y0,0),H_-1), cy1 = min(max(y1,0),H_-1); \
            int cx0 = min(max(x0,0),W_-1), cx1 = min(max(x1,0),W_-1); \
            ((int*)mp)[4] = cy0*W_ + cx0; \
            ((int*)mp)[5] = cy0*W_ + cx1; \
            ((int*)mp)[6] = cy1*W_ + cx0; \
            ((int*)mp)[7] = cy1*W_ + cx1; \
        } \
    } while (0)

    META_FROM_SOM(0, 0);
    __syncthreads();

    float acc[2][4][4];
    #pragma unroll
    for (int m = 0; m < 2; ++m)
        #pragma unroll
        for (int nt = 0; nt < 4; ++nt)
            #pragma unroll
            for (int r = 0; r < 4; ++r) acc[m][nt][r] = 0.f;

    #pragma unroll 1
    for (int k = 0; k < 9; ++k) {
        if (k) __syncthreads();

        // gather tap k -> A (hi/lo bf16, sw128, STS.128-batched)
        {
            const char* mp = sm + SM_META + (k & 1)*4096 + gpx*32;
            float w00 = ((const float*)mp)[0], w01 = ((const float*)mp)[1];
            float w10 = ((const float*)mp)[2], w11 = ((const float*)mp)[3];
            int o00 = ((const int*)mp)[4], o01 = ((const int*)mp)[5];
            int o10 = ((const int*)mp)[6], o11 = ((const int*)mp)[7];
            const float* xc = xb + (size_t)o0 * HW_;
            char* ahi = sm + SM_A;
            char* alo = sm + SM_A + 16384;
            uint32_t rowoff = (uint32_t)(gpx*128 + o0*2);
            #pragma unroll
            for (int j4 = 0; j4 < 4; ++j4) {
                uint32_t hv[4], lv[4];
                #pragma unroll
                for (int jj = 0; jj < 4; ++jj) {
                    float v0 = w00*__ldg(xc+o00) + w01*__ldg(xc+o01)
                             + w10*__ldg(xc+o10) + w11*__ldg(xc+o11);
                    const float* xc1 = xc + HW_;
                    float v1 = w00*__ldg(xc1+o00) + w01*__ldg(xc1+o01)
                             + w10*__ldg(xc1+o10) + w11*__ldg(xc1+o11);
                    xc += 2*HW_;
                    SPLIT2(v0, v1, hv[jj], lv[jj]);
                }
                uint32_t sw = sw128(rowoff + j4*16);
                *(uint4*)(ahi + sw) = make_uint4(hv[0],hv[1],hv[2],hv[3]);
                *(uint4*)(alo + sw) = make_uint4(lv[0],lv[1],lv[2],lv[3]);
            }
        }
        if (k < 8) META_FROM_SOM(k+1, (k+1)&1);

        if (k < 8) {
            uint32_t dst = smb + SM_WD + ((k+1)&1)*16384u + tid*16;
            const char* src = g_Wsplit + (k+1)*16384 + tid*16;
            #pragma unroll
            for (int j = 0; j < 4; ++j) CP16(dst + j*4096u, src + j*4096);
            CP_COMMIT();
            CP_WAIT(1);
        } else {
            CP_WAIT(0);
        }
        __syncthreads();

        // tensor GEMM: per-ks fused 3 passes (A frags loaded once)
        uint32_t wbase = smb + SM_WD + (k & 1)*16384u;
        #pragma unroll
        for (int ks = 0; ks < 4; ++ks) {
            uint32_t ah[2][4], al[2][4], bh[2][4], bl[2][4];
            LDMATRIX_X4(ah[0][0],ah[0][1],ah[0][2],ah[0][3], smb + SM_A + aoff[0][ks]);
            LDMATRIX_X4(ah[1][0],ah[1][1],ah[1][2],ah[1][3], smb + SM_A + aoff[1][ks]);
            LDMATRIX_X4(al[0][0],al[0][1],al[0][2],al[0][3], smb + SM_A + 16384u + aoff[0][ks]);
            LDMATRIX_X4(al[1][0],al[1][1],al[1][2],al[1][3], smb + SM_A + 16384u + aoff[1][ks]);
            LDMATRIX_X4(bh[0][0],bh[0][1],bh[0][2],bh[0][3], wbase + boff[0][ks]);
            LDMATRIX_X4(bh[1][0],bh[1][1],bh[1][2],bh[1][3], wbase + boff[1][ks]);
            LDMATRIX_X4(bl[0][0],bl[0][1],bl[0][2],bl[0][3], wbase + 8192u + boff[0][ks]);
            LDMATRIX_X4(bl[1][0],bl[1][1],bl[1][2],bl[1][3], wbase + 8192u + boff[1][ks]);
            #pragma unroll
            for (int m = 0; m < 2; ++m)
                #pragma unroll
                for (int nt = 0; nt < 4; ++nt) {
                    int np = nt >> 1, bi = (nt & 1)*2;
                    MMA_BF16(acc[m][nt], ah[m][0],ah[m][1],ah[m][2],ah[m][3], bh[np][bi], bh[np][bi+1]);
                    MMA_BF16(acc[m][nt], al[m][0],al[m][1],al[m][2],al[m][3], bh[np][bi], bh[np][bi+1]);
                    MMA_BF16(acc[m][nt], ah[m][0],ah[m][1],ah[m][2],ah[m][3], bl[np][bi], bl[np][bi+1]);
                }
        }
    }

    // ---- epilogue: transpose via smem (reuse WD+WOM region), coalesced store ----
    __syncthreads();
    float* ob = (float*)(sm + SM_WD);   // pitch 132 floats
    int g = l >> 2, tg = l & 3;
    #pragma unroll
    for (int m = 0; m < 2; ++m)
        #pragma unroll
        for (int nt = 0; nt < 4; ++nt) {
            int o  = o0 + nt*8 + 2*tg;
            int pa = px0 + m*16 + g;
            ob[o*132 + pa]         = acc[m][nt][0];
            ob[(o+1)*132 + pa]     = acc[m][nt][1];
            ob[o*132 + pa + 8]     = acc[m][nt][2];
            ob[(o+1)*132 + pa + 8] = acc[m][nt][3];
        }
    __syncthreads();
    for (int i = tid; i < 64*32; i += 256) {
        int o = i >> 5, seg = i & 31;
        float4 v = *(float4*)&ob[o*132 + seg*4];
        *(float4*)&out[(((size_t)b*CO + o)*HO + ho)*WO + seg*4] = v;
    }
}

// ---------------------------------------------------------------------------
extern "C" void kernel_launch(void* const* d_in, const int* in_sizes, int n_in,
                              void* d_out, int out_size) {
    const float* x      = (const float*)d_in[0];
    const float* w_off  = (const float*)d_in[1];
    const float* b_off  = (const float*)d_in[2];
    const float* w_mask = (const float*)d_in[3];
    const float* b_mask = (const float*)d_in[4];
    const float* w_conv = (const float*)d_in[5];
    float* out = (float*)d_out;

    prep_kernel<<<144, 256>>>(w_off, b_off, w_mask, b_mask, w_conv);

    cudaFuncSetAttribute((const void*)deform_kernel,
                         cudaFuncAttributeMaxDynamicSharedMemorySize, SM_TOTAL);
    deform_kernel<<<dim3(HO, B_), 256, SM_TOTAL>>>(x, out);
}

// round 8
// speedup vs baseline: 3.7608x; 1.1867x over previous
#include <cuda_runtime.h>
#include <cuda_bf16.h>
#include <math.h>
#include <stdint.h>

#define B_  8
#define CIN 64
#define H_  128
#define W_  128
#define HO  64
#define WO  128
#define CO  64
#define HW_ (H_*W_)

// Scratch (no allocations allowed -> __device__ globals)
__device__ float g_bias[32];
__device__ __align__(16) char g_Wsplit[9*16384];   // deform W: per tap hi 8KB + lo 8KB, SW128
__device__ __align__(16) char g_WomSplit[9*8192];  // conv W: per tap hi 4KB + lo 4KB, SW128
__device__ __align__(16) float g_xT[(size_t)B_*H_*W_*CIN];  // NHWC transpose of x (32MB)

__device__ __forceinline__ uint32_t smem_u32(const void* p) {
    uint32_t a;
    asm("{ .reg .u64 t; cvta.to.shared.u64 t, %1; cvt.u32.u64 %0, t; }" : "=r"(a) : "l"(p));
    return a;
}
__device__ __forceinline__ uint32_t sw128(uint32_t off) { return off ^ ((off >> 3) & 0x70); }

#define LDMATRIX_X4(r0,r1,r2,r3,addr) \
    asm volatile("ldmatrix.sync.aligned.m8n8.x4.shared.b16 {%0,%1,%2,%3}, [%4];" \
                 : "=r"(r0),"=r"(r1),"=r"(r2),"=r"(r3) : "r"(addr))

#define MMA_BF16(c, a0,a1,a2,a3, b0,b1) \
    asm volatile("mma.sync.aligned.m16n8k16.row.col.f32.bf16.bf16.f32 " \
                 "{%0,%1,%2,%3},{%4,%5,%6,%7},{%8,%9},{%0,%1,%2,%3};" \
                 : "+f"((c)[0]),"+f"((c)[1]),"+f"((c)[2]),"+f"((c)[3]) \
                 : "r"(a0),"r"(a1),"r"(a2),"r"(a3), "r"(b0),"r"(b1))

#define CP16(dst, src) \
    asm volatile("cp.async.cg.shared.global [%0], [%1], 16;" :: "r"(dst), "l"(src) : "memory")
#define CP_COMMIT() asm volatile("cp.async.commit_group;" ::: "memory")
#define CP_WAIT(n)  asm volatile("cp.async.wait_group %0;" :: "n"(n) : "memory")

// bf16 hi/lo split of (v0, v1) -> packed hi word + packed lo word
#define SPLIT2(v0, v1, h, lw) do { \
    asm("cvt.rn.bf16x2.f32 %0, %1, %2;" : "=r"(h) : "f"(v1), "f"(v0)); \
    float _h0 = __uint_as_float((h) << 16); \
    float _h1 = __uint_as_float((h) & 0xffff0000u); \
    float _l0 = (v0) - _h0, _l1 = (v1) - _h1; \
    asm("cvt.rn.bf16x2.f32 %0, %1, %2;" : "=r"(lw) : "f"(_l1), "f"(_l0)); \
} while (0)

// ---------------------------------------------------------------------------
// Kernel 0: weight repack (hi/lo split, SW128 swizzled)
// ---------------------------------------------------------------------------
__global__ void prep_kernel(const float* __restrict__ w_off, const float* __restrict__ b_off,
                            const float* __restrict__ w_mask, const float* __restrict__ b_mask,
                            const float* __restrict__ w_conv) {
    int idx = blockIdx.x * blockDim.x + threadIdx.x;
    if (idx < 9*64*64) {
        int k = idx / 4096; int r = idx & 4095; int o = r >> 6; int c = r & 63;
        float w = w_conv[(o*64 + c)*9 + k];
        __nv_bfloat16 hi = __float2bfloat16(w);
        __nv_bfloat16 lo = __float2bfloat16(w - __bfloat162float(hi));
        uint32_t sw = sw128((uint32_t)(o*128 + c*2));
        *(__nv_bfloat16*)(g_Wsplit + k*16384 + sw)        = hi;
        *(__nv_bfloat16*)(g_Wsplit + k*16384 + 8192 + sw) = lo;
    }
    if (idx < 9*32*64) {
        int k = idx / 2048; int r = idx & 2047; int o = r >> 6; int c = r & 63;
        float w = 0.f;
        if (o < 18)       w = w_off[(o*64 + c)*9 + k];
        else if (o < 27)  w = w_mask[((o-18)*64 + c)*9 + k];
        __nv_bfloat16 hi = __float2bfloat16(w);
        __nv_bfloat16 lo = __float2bfloat16(w - __bfloat162float(hi));
        uint32_t sw = sw128((uint32_t)(o*128 + c*2));
        *(__nv_bfloat16*)(g_WomSplit + k*8192 + sw)        = hi;
        *(__nv_bfloat16*)(g_WomSplit + k*8192 + 4096 + sw) = lo;
    }
    if (idx < 32) {
        float v = 0.f;
        if (idx < 18)      v = b_off[idx];
        else if (idx < 27) v = b_mask[idx - 18];
        g_bias[idx] = v;
    }
}

// ---------------------------------------------------------------------------
// Kernel 0b: NCHW -> NHWC transpose of x (for channel-contiguous gather)
// grid (4, 128, 8), block 256. Tile: one y row, 32 x, all 64 c.
// ---------------------------------------------------------------------------
__global__ void __launch_bounds__(256) transpose_kernel(const float* __restrict__ x) {
    __shared__ float t[64][33];
    int x0 = blockIdx.x * 32, y = blockIdx.y, b = blockIdx.z;
    int tx = threadIdx.x & 31, tc = threadIdx.x >> 5;   // tc 0..7
    const float* xb = x + (size_t)b * CIN * HW_ + y*W_ + x0;
    #pragma unroll
    for (int cc = 0; cc < 8; ++cc)
        t[tc + cc*8][tx] = __ldg(xb + (size_t)(tc + cc*8)*HW_ + tx);
    __syncthreads();
    float* dst = g_xT + ((size_t)b*HW_ + y*W_ + x0) * CIN;
    int c = threadIdx.x & 63, xx = threadIdx.x >> 6;    // xx 0..3
    #pragma unroll
    for (int q = 0; q < 8; ++q)
        dst[(size_t)(xx + q*4)*CIN + c] = t[c][xx + q*4];
}

// ---------------------------------------------------------------------------
// Fused kernel: phase 1 = offset/mask conv (tensor), phase 2 = gather + GEMM.
// One block = one (b, ho): D[128 px][64 o].
// ---------------------------------------------------------------------------
#define SM_A     0          // A hi 16KB + lo 16KB: row px (128B, sw128)
#define SM_WD    32768      // deform W double buffer: 2 x (hi 8KB + lo 8KB)
#define SM_WOM   65536      // conv W double buffer: 2 x (hi 4KB + lo 4KB)
#define SM_SOM   81920      // som[128 px][33 floats]
#define SM_META  99328      // meta double buffer: 2 x 128px x 32B
#define SM_TOTAL 107520     // -> 2 CTAs/SM

__global__ void __launch_bounds__(256, 2) deform_kernel(const float* __restrict__ x,
                                                        float* __restrict__ out) {
    extern __shared__ char sm[];
    const uint32_t smb = smem_u32(sm);
    int tid = threadIdx.x;
    int l = tid & 31, w = tid >> 5;
    int ho = blockIdx.x, b = blockIdx.y;
    const float* xb = x + (size_t)b * CIN * HW_;

    int px0 = (w & 3) * 32;          // px tile base (gather + mma rows)
    int o0  = (w >> 2) * 32;         // phase-2 o tile base / gather channel half
    int oh  = (w >> 2) * 16;         // phase-1 o tile base
    int gpx = px0 + l;

    // ---- ldmatrix lane offsets (relative, swizzled) ----
    uint32_t aoff[2][4], boff[2][4], b1off[4];
    {
        int arow = px0 + (l & 15);
        int acol = (l & 16) ? 16 : 0;
        #pragma unroll
        for (int m = 0; m < 2; ++m)
            #pragma unroll
            for (int ks = 0; ks < 4; ++ks)
                aoff[m][ks] = sw128((uint32_t)((arow + m*16)*128 + ks*32 + acol));
        int brow = o0 + (l & 7) + ((l & 16) ? 8 : 0);
        int bcol = (l & 8) ? 16 : 0;
        #pragma unroll
        for (int np = 0; np < 2; ++np)
            #pragma unroll
            for (int ks = 0; ks < 4; ++ks)
                boff[np][ks] = sw128((uint32_t)((brow + np*16)*128 + ks*32 + bcol));
        int b1row = oh + (l & 7) + ((l & 16) ? 8 : 0);
        #pragma unroll
        for (int ks = 0; ks < 4; ++ks)
            b1off[ks] = sw128((uint32_t)(b1row*128 + ks*32 + bcol));
    }

    // ================= PHASE 1: offset/mask conv =================
    {
        uint32_t dst = smb + SM_WOM + tid*16;
        const char* src = g_WomSplit + tid*16;
        CP16(dst, src); CP16(dst + 4096u, src + 4096);
        CP_COMMIT();
    }

    float acc1[2][2][4];
    #pragma unroll
    for (int m = 0; m < 2; ++m)
        #pragma unroll
        for (int nt = 0; nt < 2; ++nt)
            #pragma unroll
            for (int r = 0; r < 4; ++r) acc1[m][nt][r] = 0.f;

    #pragma unroll 1
    for (int k = 0; k < 9; ++k) {
        if (k) __syncthreads();

        // build A_k[px][c]: im2col row loads (NCHW, coalesced over lanes)
        {
            int gy = 2*ho - 1 + (k/3);
            int gx = gpx - 1 + (k%3);
            bool vld = (gy >= 0) && (gx >= 0) && (gx < W_);
            char* ahi = sm + SM_A;
            char* alo = sm + SM_A + 16384;
            uint32_t rowoff = (uint32_t)(gpx*128 + o0*2);
            const float* xc = xb + (size_t)o0 * HW_ + gy*W_ + gx;
            #pragma unroll
            for (int j4 = 0; j4 < 4; ++j4) {
                uint32_t hv[4], lv[4];
                #pragma unroll
                for (int jj = 0; jj < 4; ++jj) {
                    float v0 = vld ? __ldg(xc)       : 0.f;
                    float v1 = vld ? __ldg(xc + HW_) : 0.f;
                    xc += 2*HW_;
                    SPLIT2(v0, v1, hv[jj], lv[jj]);
                }
                uint32_t sw = sw128(rowoff + j4*16);
                *(uint4*)(ahi + sw) = make_uint4(hv[0],hv[1],hv[2],hv[3]);
                *(uint4*)(alo + sw) = make_uint4(lv[0],lv[1],lv[2],lv[3]);
            }
        }
        if (k < 8) {
            uint32_t dst = smb + SM_WOM + ((k+1)&1)*8192u + tid*16;
            const char* src = g_WomSplit + (k+1)*8192 + tid*16;
            CP16(dst, src); CP16(dst + 4096u, src + 4096);
            CP_COMMIT();
            CP_WAIT(1);
        } else {
            CP_WAIT(0);
        }
        __syncthreads();

        uint32_t wbase = smb + SM_WOM + (k & 1)*8192u;
        #pragma unroll
        for (int ks = 0; ks < 4; ++ks) {
            uint32_t ah[2][4], al[2][4], bh[4], bl[4];
            LDMATRIX_X4(ah[0][0],ah[0][1],ah[0][2],ah[0][3], smb + SM_A + aoff[0][ks]);
            LDMATRIX_X4(ah[1][0],ah[1][1],ah[1][2],ah[1][3], smb + SM_A + aoff[1][ks]);
            LDMATRIX_X4(al[0][0],al[0][1],al[0][2],al[0][3], smb + SM_A + 16384u + aoff[0][ks]);
            LDMATRIX_X4(al[1][0],al[1][1],al[1][2],al[1][3], smb + SM_A + 16384u + aoff[1][ks]);
            LDMATRIX_X4(bh[0],bh[1],bh[2],bh[3], wbase + b1off[ks]);
            LDMATRIX_X4(bl[0],bl[1],bl[2],bl[3], wbase + 4096u + b1off[ks]);
            #pragma unroll
            for (int m = 0; m < 2; ++m)
                #pragma unroll
                for (int nt = 0; nt < 2; ++nt) {
                    MMA_BF16(acc1[m][nt], ah[m][0],ah[m][1],ah[m][2],ah[m][3], bh[nt*2], bh[nt*2+1]);
                    MMA_BF16(acc1[m][nt], al[m][0],al[m][1],al[m][2],al[m][3], bh[nt*2], bh[nt*2+1]);
                    MMA_BF16(acc1[m][nt], ah[m][0],ah[m][1],ah[m][2],ah[m][3], bl[nt*2], bl[nt*2+1]);
                }
        }
    }

    // write som[px][o] = acc + bias
    {
        float* som = (float*)(sm + SM_SOM);
        int g = l >> 2, tg = l & 3;
        #pragma unroll
        for (int m = 0; m < 2; ++m)
            #pragma unroll
            for (int nt = 0; nt < 2; ++nt) {
                int o  = oh + nt*8 + 2*tg;
                int pa = px0 + m*16 + g;
                som[pa*33 + o]       = acc1[m][nt][0] + g_bias[o];
                som[pa*33 + o + 1]   = acc1[m][nt][1] + g_bias[o+1];
                som[(pa+8)*33 + o]   = acc1[m][nt][2] + g_bias[o];
                som[(pa+8)*33 + o+1] = acc1[m][nt][3] + g_bias[o+1];
            }
    }
    // stage deform W tap 0
    {
        uint32_t dst = smb + SM_WD + tid*16;
        const char* src = g_Wsplit + tid*16;
        #pragma unroll
        for (int j = 0; j < 4; ++j) CP16(dst + j*4096u, src + j*4096);
        CP_COMMIT();
    }
    __syncthreads();   // som visible

    // ================= PHASE 2: gather + deform GEMM =================
    // meta: 4 corner weights + 4 corner byte-offsets into NHWC row (x256B)
    #define META_FROM_SOM(TAP, BUF) do { \
        if (tid < 128) { \
            int px = tid; \
            const float* som = (const float*)(sm + SM_SOM); \
            float offy = som[px*33 + 2*(TAP)]; \
            float offx = som[px*33 + 2*(TAP) + 1]; \
            float mr   = som[px*33 + 18 + (TAP)]; \
            float mk   = 1.f / (1.f + expf(-mr)); \
            float py  = offy + (float)((TAP)/3) + (float)(2*ho - 1); \
            float pxx = offx + (float)((TAP)%3) + (float)(px - 1); \
            float y0f = floorf(py), x0f = floorf(pxx); \
            float dy = py - y0f,  dx = pxx - x0f; \
            int y0 = (int)y0f, x0 = (int)x0f; \
            int y1 = y0 + 1,   x1 = x0 + 1; \
            bool vy0 = (y0>=0)&&(y0<H_), vy1 = (y1>=0)&&(y1<H_); \
            bool vx0 = (x0>=0)&&(x0<W_), vx1 = (x1>=0)&&(x1<W_); \
            float* mp = (float*)(sm + SM_META + (BUF)*4096 + px*32); \
            mp[0] = (1.f-dy)*(1.f-dx)*mk * ((vy0&&vx0)?1.f:0.f); \
            mp[1] = (1.f-dy)*dx      *mk * ((vy0&&vx1)?1.f:0.f); \
            mp[2] = dy*(1.f-dx)      *mk * ((vy1&&vx0)?1.f:0.f); \
            mp[3] = dy*dx            *mk * ((vy1&&vx1)?1.f:0.f); \
            int cy0 = min(max(y0,0),H_-1), cy1 = min(max(y1,0),H_-1); \
            int cx0 = min(max(x0,0),W_-1), cx1 = min(max(x1,0),W_-1); \
            ((int*)mp)[4] = (cy0*W_ + cx0) << 8; \
            ((int*)mp)[5] = (cy0*W_ + cx1) << 8; \
            ((int*)mp)[6] = (cy1*W_ + cx0) << 8; \
            ((int*)mp)[7] = (cy1*W_ + cx1) << 8; \
        } \
    } while (0)

    META_FROM_SOM(0, 0);
    __syncthreads();

    float acc[2][4][4];
    #pragma unroll
    for (int m = 0; m < 2; ++m)
        #pragma unroll
        for (int nt = 0; nt < 4; ++nt)
            #pragma unroll
            for (int r = 0; r < 4; ++r) acc[m][nt][r] = 0.f;

    const char* xTb = (const char*)(g_xT + (size_t)b * HW_ * CIN);
    int sub = l >> 3;          // px within 4-px group
    int ch4 = l & 7;           // 4-channel chunk within 32-ch half
    uint32_t chbyte = (uint32_t)(o0*4 + ch4*16);   // byte offset within 256B NHWC row

    #pragma unroll 1
    for (int k = 0; k < 9; ++k) {
        if (k) __syncthreads();

        // gather tap k -> A. NHWC: one LDG.128 = 4 px x 1 corner x 4 ch (coalesced).
        {
            const char* mpb = sm + SM_META + (k & 1)*4096;
            char* ahi = sm + SM_A;
            char* alo = sm + SM_A + 16384;
            #pragma unroll
            for (int g8 = 0; g8 < 8; ++g8) {
                int px = px0 + g8*4 + sub;
                const float* mp = (const float*)(mpb + px*32);
                float4 wv = *(const float4*)mp;
                int4   ov = *(const int4*)(mp + 4);
                float4 c00 = *(const float4*)(xTb + (uint32_t)ov.x + chbyte);
                float4 c01 = *(const float4*)(xTb + (uint32_t)ov.y + chbyte);
                float4 c10 = *(const float4*)(xTb + (uint32_t)ov.z + chbyte);
                float4 c11 = *(const float4*)(xTb + (uint32_t)ov.w + chbyte);
                float v0 = wv.x*c00.x + wv.y*c01.x + wv.z*c10.x + wv.w*c11.x;
                float v1 = wv.x*c00.y + wv.y*c01.y + wv.z*c10.y + wv.w*c11.y;
                float v2 = wv.x*c00.z + wv.y*c01.z + wv.z*c10.z + wv.w*c11.z;
                float v3 = wv.x*c00.w + wv.y*c01.w + wv.z*c10.w + wv.w*c11.w;
                uint32_t h0, l0, h1, l1;
                SPLIT2(v0, v1, h0, l0);
                SPLIT2(v2, v3, h1, l1);
                uint32_t sw = sw128((uint32_t)(px*128) + (uint32_t)(o0*2) + (uint32_t)(ch4*8));
                *(uint2*)(ahi + sw) = make_uint2(h0, h1);
                *(uint2*)(alo + sw) = make_uint2(l0, l1);
            }
        }
        if (k < 8) META_FROM_SOM(k+1, (k+1)&1);

        if (k < 8) {
            uint32_t dst = smb + SM_WD + ((k+1)&1)*16384u + tid*16;
            const char* src = g_Wsplit + (k+1)*16384 + tid*16;
            #pragma unroll
            for (int j = 0; j < 4; ++j) CP16(dst + j*4096u, src + j*4096);
            CP_COMMIT();
            CP_WAIT(1);
        } else {
            CP_WAIT(0);
        }
        __syncthreads();

        // tensor GEMM: per-ks fused 3 passes (A frags loaded once)
        uint32_t wbase = smb + SM_WD + (k & 1)*16384u;
        #pragma unroll
        for (int ks = 0; ks < 4; ++ks) {
            uint32_t ah[2][4], al[2][4], bh[2][4], bl[2][4];
            LDMATRIX_X4(ah[0][0],ah[0][1],ah[0][2],ah[0][3], smb + SM_A + aoff[0][ks]);
            LDMATRIX_X4(ah[1][0],ah[1][1],ah[1][2],ah[1][3], smb + SM_A + aoff[1][ks]);
            LDMATRIX_X4(al[0][0],al[0][1],al[0][2],al[0][3], smb + SM_A + 16384u + aoff[0][ks]);
            LDMATRIX_X4(al[1][0],al[1][1],al[1][2],al[1][3], smb + SM_A + 16384u + aoff[1][ks]);
            LDMATRIX_X4(bh[0][0],bh[0][1],bh[0][2],bh[0][3], wbase + boff[0][ks]);
            LDMATRIX_X4(bh[1][0],bh[1][1],bh[1][2],bh[1][3], wbase + boff[1][ks]);
            LDMATRIX_X4(bl[0][0],bl[0][1],bl[0][2],bl[0][3], wbase + 8192u + boff[0][ks]);
            LDMATRIX_X4(bl[1][0],bl[1][1],bl[1][2],bl[1][3], wbase + 8192u + boff[1][ks]);
            #pragma unroll
            for (int m = 0; m < 2; ++m)
                #pragma unroll
                for (int nt = 0; nt < 4; ++nt) {
                    int np = nt >> 1, bi = (nt & 1)*2;
                    MMA_BF16(acc[m][nt], ah[m][0],ah[m][1],ah[m][2],ah[m][3], bh[np][bi], bh[np][bi+1]);
                    MMA_BF16(acc[m][nt], al[m][0],al[m][1],al[m][2],al[m][3], bh[np][bi], bh[np][bi+1]);
                    MMA_BF16(acc[m][nt], ah[m][0],ah[m][1],ah[m][2],ah[m][3], bl[np][bi], bl[np][bi+1]);
                }
        }
    }

    // ---- epilogue: transpose via smem (reuse WD+WOM region), coalesced store ----
    __syncthreads();
    float* ob = (float*)(sm + SM_WD);   // pitch 132 floats
    int g = l >> 2, tg = l & 3;
    #pragma unroll
    for (int m = 0; m < 2; ++m)
        #pragma unroll
        for (int nt = 0; nt < 4; ++nt) {
            int o  = o0 + nt*8 + 2*tg;
            int pa = px0 + m*16 + g;
            ob[o*132 + pa]         = acc[m][nt][0];
            ob[(o+1)*132 + pa]     = acc[m][nt][1];
            ob[o*132 + pa + 8]     = acc[m][nt][2];
            ob[(o+1)*132 + pa + 8] = acc[m][nt][3];
        }
    __syncthreads();
    for (int i = tid; i < 64*32; i += 256) {
        int o = i >> 5, seg = i & 31;
        float4 v = *(float4*)&ob[o*132 + seg*4];
        *(float4*)&out[(((size_t)b*CO + o)*HO + ho)*WO + seg*4] = v;
    }
}

// ---------------------------------------------------------------------------
extern "C" void kernel_launch(void* const* d_in, const int* in_sizes, int n_in,
                              void* d_out, int out_size) {
    const float* x      = (const float*)d_in[0];
    const float* w_off  = (const float*)d_in[1];
    const float* b_off  = (const float*)d_in[2];
    const float* w_mask = (const float*)d_in[3];
    const float* b_mask = (const float*)d_in[4];
    const float* w_conv = (const float*)d_in[5];
    float* out = (float*)d_out;

    prep_kernel<<<144, 256>>>(w_off, b_off, w_mask, b_mask, w_conv);
    transpose_kernel<<<dim3(4, 128, 8), 256>>>(x);

    cudaFuncSetAttribute((const void*)deform_kernel,
                         cudaFuncAttributeMaxDynamicSharedMemorySize, SM_TOTAL);
    deform_kernel<<<dim3(HO, B_), 256, SM_TOTAL>>>(x, out);
}